// round 10
// baseline (speedup 1.0000x reference)
#include <cuda_runtime.h>
#include <cuda_fp16.h>
#include <cstdint>
#include <math.h>

// ---------------------------------------------------------------- constants
#define BSQ   4096
#define CDIM  1024
#define NTOT  8192
#define HD    1024
#define SCALE2_F 0.03125f              // (1024^-0.25)^2 = 1/32

// GEMM config: CTA 128x128, k-chunk 64, 3-stage cp.async pipeline
#define ROWB      144                  // smem row stride bytes (64 f16 data + pad)
#define MAT_BYTES (128 * ROWB)         // 18432
#define STG_BYTES (4 * MAT_BYTES)      // Ah,Al,Bh,Bl = 73728
#define NST       3
#define SMEM_GEMM (NST * STG_BYTES)    // 221184

// ---------------------------------------------------------------- scratch
static __device__ float   g_S  [(size_t)NTOT*NTOT];            // 256 MB
static __device__ __half  g_ch [(size_t)NTOT*CDIM],  g_cl [(size_t)NTOT*CDIM];
static __device__ __half  g_wqTh[(size_t)CDIM*HD],   g_wqTl[(size_t)CDIM*HD];
static __device__ __half  g_wkTh[(size_t)CDIM*HD],   g_wkTl[(size_t)CDIM*HD];
static __device__ __half  g_mwth[(size_t)HD*CDIM],   g_mwtl[(size_t)HD*CDIM];
static __device__ __half  g_zh [(size_t)NTOT*HD],    g_zl [(size_t)NTOT*HD];
static __device__ __half  g_wpsh[(size_t)HD*HD],     g_wpsl[(size_t)HD*HD];
static __device__ __half  g_wpqh[(size_t)HD*HD],     g_wpql[(size_t)HD*HD];
static __device__ __half  g_pcqh[(size_t)BSQ*BSQ];             // P quadrants, f16 only
static __device__ __half  g_pqch[(size_t)BSQ*BSQ];
static __device__ __half  g_qTh[(size_t)CDIM*BSQ],   g_qTl[(size_t)CDIM*BSQ];
static __device__ __half  g_sTh[(size_t)CDIM*BSQ],   g_sTl[(size_t)CDIM*BSQ];
static __device__ __half  g_t0h[(size_t)BSQ*HD];               // t, f16 only
static __device__ __half  g_t1h[(size_t)BSQ*HD];

// ---------------------------------------------------------------- helpers
__device__ __forceinline__ uint32_t smem_u32(const void* p) {
    uint32_t a;
    asm("{ .reg .u64 t; cvta.to.shared.u64 t, %1; cvt.u32.u64 %0, t; }" : "=r"(a) : "l"(p));
    return a;
}
__device__ __forceinline__ void cp16(uint32_t dst, const void* src) {
    asm volatile("cp.async.cg.shared.global [%0], [%1], 16;" :: "r"(dst), "l"(src) : "memory");
}
#define CP_COMMIT() asm volatile("cp.async.commit_group;" ::: "memory")
#define CP_WAIT(n)  asm volatile("cp.async.wait_group %0;" :: "n"(n) : "memory")

#define LDSM4(r, a) \
    asm volatile("ldmatrix.sync.aligned.m8n8.x4.shared.b16 {%0,%1,%2,%3}, [%4];" \
        : "=r"((r)[0]), "=r"((r)[1]), "=r"((r)[2]), "=r"((r)[3]) : "r"(a))

#define MMA(d, a, b0, b1) \
    asm volatile("mma.sync.aligned.m16n8k16.row.col.f32.f16.f16.f32 " \
        "{%0,%1,%2,%3}, {%4,%5,%6,%7}, {%8,%9}, {%0,%1,%2,%3};" \
        : "+f"((d)[0]), "+f"((d)[1]), "+f"((d)[2]), "+f"((d)[3]) \
        : "r"((a)[0]), "r"((a)[1]), "r"((a)[2]), "r"((a)[3]), "r"(b0), "r"(b1))

__device__ __forceinline__ unsigned pack2(__half a, __half b) {
    unsigned short x = *reinterpret_cast<unsigned short*>(&a);
    unsigned short y = *reinterpret_cast<unsigned short*>(&b);
    return (unsigned)x | ((unsigned)y << 16);
}
__device__ __forceinline__ void wr_hl4(__half* H, __half* L, size_t off, float4 v) {
    __half h0 = __float2half(v.x), h1 = __float2half(v.y);
    __half h2 = __float2half(v.z), h3 = __float2half(v.w);
    uint2 hu; hu.x = pack2(h0, h1); hu.y = pack2(h2, h3);
    uint2 lu;
    lu.x = pack2(__float2half(v.x - __half2float(h0)),
                 __float2half(v.y - __half2float(h1)));
    lu.y = pack2(__float2half(v.z - __half2float(h2)),
                 __float2half(v.w - __half2float(h3)));
    *reinterpret_cast<uint2*>(H + off) = hu;
    *reinterpret_cast<uint2*>(L + off) = lu;
}

// ---------------------------------------------------------------- HMMA GEMM
// NPROD==3: D = alpha*(Ah@Bh^T + Ah@Bl^T + Al@Bh^T)   (~2^-23 eff. precision)
// NPROD==2: D = alpha*(Ah@Bh^T + Ah@Bl^T)             (A rounded to f16, ~2^-12)
// A: [M][K] row-major f16 (ldA), B: [N][K] row-major f16 (ldB).
// Out: Cf (f32) if non-null, else Ch (+ Cl when non-null) f16.
// K % 64 == 0, K >= 128.
template <int NPROD>
__global__ __launch_bounds__(256, 1) void hmma_gemm(
    const __half* __restrict__ Ah, const __half* __restrict__ Al, size_t ldA,
    const __half* __restrict__ Bh, const __half* __restrict__ Bl, size_t ldB,
    int K, float alpha,
    float* __restrict__ Cf, __half* __restrict__ Ch, __half* __restrict__ Cl,
    int ldc)
{
    extern __shared__ char dynsm[];
    const uint32_t sbase = smem_u32(dynsm);

    const int tid  = threadIdx.x;
    const int wid  = tid >> 5;
    const int lane = tid & 31;
    const int mBase = blockIdx.y * 128;
    const int nBase = blockIdx.x * 128;
    const int nch = K >> 6;

    const int wm = wid & 3, wn = wid >> 2;

    // ---- load geometry: sel 0..3 -> Ah,Al,Bh,Bl; 2 rows/thread, 8 cp16/row
    const int sel  = tid >> 6;
    const int lrow = (tid & 63) * 2;
    const __half* gsrc;
    size_t gld;
    if (sel == 0)      { gsrc = Ah + (size_t)(mBase + lrow) * ldA; gld = ldA; }
    else if (sel == 1) { gsrc = Al + (size_t)(mBase + lrow) * ldA; gld = ldA; }
    else if (sel == 2) { gsrc = Bh + (size_t)(nBase + lrow) * ldB; gld = ldB; }
    else               { gsrc = Bl + (size_t)(nBase + lrow) * ldB; gld = ldB; }
    const uint32_t sdst0 = sbase + sel * MAT_BYTES + lrow * ROWB;
    const bool do_load = (NPROD == 3) || (sel != 1);

    #define LOAD_CHUNK(stg, k0) do {                                    \
        if (do_load) {                                                   \
            const uint32_t _d = sdst0 + (stg) * STG_BYTES;               \
            const __half* _s = gsrc + (k0);                              \
            _Pragma("unroll")                                            \
            for (int _j = 0; _j < 8; ++_j) {                             \
                cp16(_d + _j * 16,        _s + _j * 8);                  \
                cp16(_d + ROWB + _j * 16, _s + gld + _j * 8);            \
            }                                                            \
        }                                                                \
    } while (0)

    const int l15 = lane & 15;
    const int lc8 = (lane >> 4) << 3;

    float acc[2][8][4];
    #pragma unroll
    for (int i = 0; i < 2; ++i)
        #pragma unroll
        for (int j = 0; j < 8; ++j)
            #pragma unroll
            for (int q = 0; q < 4; ++q) acc[i][j][q] = 0.0f;

    // prologue: chunks 0,1 in flight
    LOAD_CHUNK(0, 0);
    CP_COMMIT();
    LOAD_CHUNK(1, 64);
    CP_COMMIT();

    for (int i = 0; i < nch; ++i) {
        CP_WAIT(1);
        __syncthreads();
        if (i + 2 < nch) { LOAD_CHUNK((i + 2) % NST, (i + 2) << 6); }
        CP_COMMIT();

        const uint32_t stg = sbase + (i % NST) * STG_BYTES;
        #pragma unroll
        for (int kk = 0; kk < 64; kk += 16) {
            uint32_t ah[2][4], al[2][4], bh[4][4], bl[4][4];
            #pragma unroll
            for (int mi = 0; mi < 2; ++mi) {
                const uint32_t ao = stg + (wm*32 + mi*16 + l15) * ROWB + (kk + lc8) * 2;
                LDSM4(ah[mi], ao);
                if (NPROD == 3) LDSM4(al[mi], ao + MAT_BYTES);
            }
            #pragma unroll
            for (int g = 0; g < 4; ++g) {
                const uint32_t bo = stg + 2*MAT_BYTES + (wn*64 + g*16 + l15) * ROWB + (kk + lc8) * 2;
                LDSM4(bh[g], bo);
                LDSM4(bl[g], bo + MAT_BYTES);
            }
            // product-major: dependent MMAs on same acc are 16 apart
            #pragma unroll
            for (int mi = 0; mi < 2; ++mi)
                #pragma unroll
                for (int g = 0; g < 4; ++g) {
                    MMA(acc[mi][2*g+0], ah[mi], bh[g][0], bh[g][2]);
                    MMA(acc[mi][2*g+1], ah[mi], bh[g][1], bh[g][3]);
                }
            #pragma unroll
            for (int mi = 0; mi < 2; ++mi)
                #pragma unroll
                for (int g = 0; g < 4; ++g) {
                    MMA(acc[mi][2*g+0], ah[mi], bl[g][0], bl[g][2]);
                    MMA(acc[mi][2*g+1], ah[mi], bl[g][1], bl[g][3]);
                }
            if (NPROD == 3) {
                #pragma unroll
                for (int mi = 0; mi < 2; ++mi)
                    #pragma unroll
                    for (int g = 0; g < 4; ++g) {
                        MMA(acc[mi][2*g+0], al[mi], bh[g][0], bh[g][2]);
                        MMA(acc[mi][2*g+1], al[mi], bh[g][1], bh[g][3]);
                    }
            }
        }
    }

    // ---- epilogue
    const int g4 = lane >> 2, t4 = lane & 3;
    #pragma unroll
    for (int mi = 0; mi < 2; ++mi) {
        #pragma unroll
        for (int nj = 0; nj < 8; ++nj) {
            const int r0 = mBase + wm*32 + mi*16 + g4;
            const int c0 = nBase + wn*64 + nj*8 + t4*2;
            float v0 = acc[mi][nj][0] * alpha, v1 = acc[mi][nj][1] * alpha;
            float v2 = acc[mi][nj][2] * alpha, v3 = acc[mi][nj][3] * alpha;
            if (Cf) {
                *reinterpret_cast<float2*>(Cf + (size_t)r0 * ldc + c0)       = make_float2(v0, v1);
                *reinterpret_cast<float2*>(Cf + (size_t)(r0+8) * ldc + c0)   = make_float2(v2, v3);
            } else {
                __half h0 = __float2half(v0), h1 = __float2half(v1);
                __half h2 = __float2half(v2), h3 = __float2half(v3);
                *reinterpret_cast<unsigned*>(Ch + (size_t)r0 * ldc + c0)     = pack2(h0, h1);
                *reinterpret_cast<unsigned*>(Ch + (size_t)(r0+8) * ldc + c0) = pack2(h2, h3);
                if (Cl) {
                    *reinterpret_cast<unsigned*>(Cl + (size_t)r0 * ldc + c0) =
                        pack2(__float2half(v0 - __half2float(h0)),
                              __float2half(v1 - __half2float(h1)));
                    *reinterpret_cast<unsigned*>(Cl + (size_t)(r0+8) * ldc + c0) =
                        pack2(__float2half(v2 - __half2float(h2)),
                              __float2half(v3 - __half2float(h3)));
                }
            }
        }
    }
}

// ---------------------------------------------------------------- small kernels
__global__ __launch_bounds__(256) void build_c_split(const float4* __restrict__ s,
                                                     const float4* __restrict__ tg,
                                                     const float4* __restrict__ q)
{
    const size_t i = (size_t)blockIdx.x * blockDim.x + threadIdx.x;
    float4 a = s[i], b = tg[i];
    float4 r; r.x = a.x + b.x; r.y = a.y + b.y; r.z = a.z + b.z; r.w = a.w + b.w;
    wr_hl4(g_ch, g_cl, i * 4, r);
    float4 qq = q[i];
    wr_hl4(g_ch, g_cl, (size_t)BSQ * CDIM + i * 4, qq);
}

__global__ __launch_bounds__(256) void cvt_w(const float4* __restrict__ w,
                                             __half* __restrict__ H,
                                             __half* __restrict__ L)
{
    const size_t i = (size_t)blockIdx.x * blockDim.x + threadIdx.x;
    wr_hl4(H, L, i * 4, w[i]);
}

// transpose fp32 [R x C] -> f16 hi/lo [C x R]
__global__ __launch_bounds__(256) void transpose_cvt(const float* __restrict__ in,
                                                     __half* __restrict__ oh,
                                                     __half* __restrict__ ol,
                                                     int R, int C)
{
    __shared__ float t[32][33];
    const int tx = threadIdx.x, ty = threadIdx.y;
    const int x = blockIdx.x * 32 + tx;
    #pragma unroll
    for (int j = 0; j < 4; ++j) {
        const int y = blockIdx.y * 32 + ty + j * 8;
        t[ty + j*8][tx] = in[(size_t)y * C + x];
    }
    __syncthreads();
    const int ox = blockIdx.y * 32 + tx;
    #pragma unroll
    for (int j = 0; j < 4; ++j) {
        const int oy = blockIdx.x * 32 + ty + j * 8;
        float v = t[tx][ty + j*8];
        __half h = __float2half(v);
        oh[(size_t)oy * R + ox] = h;
        ol[(size_t)oy * R + ox] = __float2half(v - __half2float(h));
    }
}

// softmax over 8192-wide rows; emit needed quadrant as f16 (hi only — P@V is 2-prod)
__global__ __launch_bounds__(512) void softmax_fused(const float* __restrict__ S)
{
    const float* p = S + (size_t)blockIdx.x * NTOT;
    const int t = threadIdx.x;
    float v[16];
    float m = -1e30f;
    #pragma unroll
    for (int i = 0; i < 16; ++i) { v[i] = p[t + i * 512]; m = fmaxf(m, v[i]); }

    __shared__ float red[16];
    #pragma unroll
    for (int o = 16; o; o >>= 1) m = fmaxf(m, __shfl_xor_sync(0xffffffffu, m, o));
    if ((t & 31) == 0) red[t >> 5] = m;
    __syncthreads();
    float mm = red[0];
    #pragma unroll
    for (int i = 1; i < 16; ++i) mm = fmaxf(mm, red[i]);

    float sum = 0.0f;
    #pragma unroll
    for (int i = 0; i < 16; ++i) { v[i] = __expf(v[i] - mm); sum += v[i]; }
    #pragma unroll
    for (int o = 16; o; o >>= 1) sum += __shfl_xor_sync(0xffffffffu, sum, o);
    __syncthreads();
    if ((t & 31) == 0) red[t >> 5] = sum;
    __syncthreads();
    float tot = 0.0f;
    #pragma unroll
    for (int i = 0; i < 16; ++i) tot += red[i];
    const float rcp = 1.0f / tot;

    if (blockIdx.x < BSQ) {
        const size_t rb = (size_t)blockIdx.x * BSQ;
        #pragma unroll
        for (int i = 8; i < 16; ++i) {
            const int col = t + (i - 8) * 512;
            g_pcqh[rb + col] = __float2half(v[i] * rcp);
        }
    } else {
        const size_t rb = (size_t)(blockIdx.x - BSQ) * BSQ;
        #pragma unroll
        for (int i = 0; i < 8; ++i) {
            const int col = t + i * 512;
            g_pqch[rb + col] = __float2half(v[i] * rcp);
        }
    }
}

// ---------------------------------------------------------------- host
static void run_gemm(const __half* Ah, const __half* Al, size_t ldA,
                     const __half* Bh, const __half* Bl, size_t ldB,
                     int M, int N, int K, float alpha,
                     float* Cf, __half* Ch, __half* Cl, int ldc,
                     bool two_prod = false)
{
    if (two_prod)
        hmma_gemm<2><<<dim3(N / 128, M / 128), 256, SMEM_GEMM>>>(
            Ah, Al, ldA, Bh, Bl, ldB, K, alpha, Cf, Ch, Cl, ldc);
    else
        hmma_gemm<3><<<dim3(N / 128, M / 128), 256, SMEM_GEMM>>>(
            Ah, Al, ldA, Bh, Bl, ldB, K, alpha, Cf, Ch, Cl, ldc);
}

extern "C" void kernel_launch(void* const* d_in, const int* in_sizes, int n_in,
                              void* d_out, int out_size)
{
    const float* query = (const float*)d_in[0];
    const float* s     = (const float*)d_in[1];
    const float* tg    = (const float*)d_in[2];
    const float* Wqkv  = (const float*)d_in[3];
    const float* Wps   = (const float*)d_in[4];
    const float* Wpq   = (const float*)d_in[5];
    float* out = (float*)d_out;

    void* p;
    cudaGetSymbolAddress(&p, g_S);    float* S = (float*)p;
    cudaGetSymbolAddress(&p, g_ch);   __half* ch = (__half*)p;
    cudaGetSymbolAddress(&p, g_cl);   __half* cl = (__half*)p;
    cudaGetSymbolAddress(&p, g_wqTh); __half* wqTh = (__half*)p;
    cudaGetSymbolAddress(&p, g_wqTl); __half* wqTl = (__half*)p;
    cudaGetSymbolAddress(&p, g_wkTh); __half* wkTh = (__half*)p;
    cudaGetSymbolAddress(&p, g_wkTl); __half* wkTl = (__half*)p;
    cudaGetSymbolAddress(&p, g_mwth); __half* mwth = (__half*)p;
    cudaGetSymbolAddress(&p, g_mwtl); __half* mwtl = (__half*)p;
    cudaGetSymbolAddress(&p, g_zh);   __half* zh = (__half*)p;
    cudaGetSymbolAddress(&p, g_zl);   __half* zl = (__half*)p;
    cudaGetSymbolAddress(&p, g_wpsh); __half* wpsh = (__half*)p;
    cudaGetSymbolAddress(&p, g_wpsl); __half* wpsl = (__half*)p;
    cudaGetSymbolAddress(&p, g_wpqh); __half* wpqh = (__half*)p;
    cudaGetSymbolAddress(&p, g_wpql); __half* wpql = (__half*)p;
    cudaGetSymbolAddress(&p, g_pcqh); __half* pcqh = (__half*)p;
    cudaGetSymbolAddress(&p, g_pqch); __half* pqch = (__half*)p;
    cudaGetSymbolAddress(&p, g_qTh);  __half* qTh = (__half*)p;
    cudaGetSymbolAddress(&p, g_qTl);  __half* qTl = (__half*)p;
    cudaGetSymbolAddress(&p, g_sTh);  __half* sTh = (__half*)p;
    cudaGetSymbolAddress(&p, g_sTl);  __half* sTl = (__half*)p;
    cudaGetSymbolAddress(&p, g_t0h);  __half* t0h = (__half*)p;
    cudaGetSymbolAddress(&p, g_t1h);  __half* t1h = (__half*)p;

    cudaFuncSetAttribute(hmma_gemm<3>, cudaFuncAttributeMaxDynamicSharedMemorySize, SMEM_GEMM);
    cudaFuncSetAttribute(hmma_gemm<2>, cudaFuncAttributeMaxDynamicSharedMemorySize, SMEM_GEMM);

    // 1) c = [s+TG ; query] -> f16 hi/lo
    build_c_split<<<(BSQ * CDIM / 4) / 256, 256>>>(
        (const float4*)s, (const float4*)tg, (const float4*)query);

    // 2) projection weight conversions
    cvt_w<<<(HD * HD / 4) / 256, 256>>>((const float4*)Wps, wpsh, wpsl);
    cvt_w<<<(HD * HD / 4) / 256, 256>>>((const float4*)Wpq, wpqh, wpql);

    // 3) transposes: query^T, s^T (attn@V B operands), Wq^T, Wk^T
    transpose_cvt<<<dim3(CDIM / 32, BSQ / 32), dim3(32, 8)>>>(query, qTh, qTl, BSQ, CDIM);
    transpose_cvt<<<dim3(CDIM / 32, BSQ / 32), dim3(32, 8)>>>(s, sTh, sTl, BSQ, CDIM);
    transpose_cvt<<<dim3(CDIM / 32, HD / 32), dim3(32, 8)>>>(Wqkv, wqTh, wqTl, HD, CDIM);
    transpose_cvt<<<dim3(CDIM / 32, HD / 32), dim3(32, 8)>>>(Wqkv + (size_t)HD * CDIM,
                                                             wkTh, wkTl, HD, CDIM);

    // 4) MwT = SCALE^2 * Wk^T @ Wq  -> f16 hi/lo [1024 x 1024]  (3-prod)
    run_gemm(wkTh, wkTl, HD, wqTh, wqTl, HD,
             CDIM, CDIM, HD, SCALE2_F, nullptr, mwth, mwtl, CDIM);

    // 5) Z = c @ MwT^T  -> f16 hi/lo [8192 x 1024]  (3-prod, logit path)
    run_gemm(ch, cl, CDIM, mwth, mwtl, CDIM,
             NTOT, HD, CDIM, 1.0f, nullptr, zh, zl, HD);

    // 6) S = Z @ c^T (f32) [8192 x 8192] — 2-prod (Z rounded to f16)
    run_gemm(zh, zl, HD, ch, cl, CDIM,
             NTOT, NTOT, HD, 1.0f, S, nullptr, nullptr, NTOT, /*two_prod=*/true);

    // 7) softmax + quadrant split -> f16 (hi only)
    softmax_fused<<<NTOT, 512>>>(S);

    // 8) t0 = Pcq @ query ; t1 = Pqc @ s  -> f16 [4096 x 1024] — 2-prod (P f16)
    run_gemm(pcqh, nullptr, BSQ, qTh, qTl, BSQ,
             BSQ, HD, BSQ, 1.0f, nullptr, t0h, nullptr, HD, /*two_prod=*/true);
    run_gemm(pqch, nullptr, BSQ, sTh, sTl, BSQ,
             BSQ, HD, BSQ, 1.0f, nullptr, t1h, nullptr, HD, /*two_prod=*/true);

    // 9) x_s = t0 @ Wps^T ; x_q = t1 @ Wpq^T (f32 out) — 2-prod (t f16)
    run_gemm(t0h, nullptr, HD, wpsh, wpsl, HD,
             BSQ, HD, HD, 1.0f, out, nullptr, nullptr, HD, /*two_prod=*/true);
    run_gemm(t1h, nullptr, HD, wpqh, wpql, HD,
             BSQ, HD, HD, 1.0f, out + (size_t)BSQ * HD, nullptr, nullptr, HD, /*two_prod=*/true);
}

// round 11
// speedup vs baseline: 1.5497x; 1.5497x over previous
#include <cuda_runtime.h>
#include <cuda_fp16.h>
#include <cstdint>
#include <math.h>

// ---------------------------------------------------------------- constants
#define BSQ   4096
#define CDIM  1024
#define NTOT  8192
#define HD    1024
#define SCALE2_F 0.03125f              // (1024^-0.25)^2 = 1/32

// GEMM config: CTA 128x128, k-chunk 64
// 3-prod: 4 mats/stage, 3 stages.  2-prod: 3 mats/stage, 4 stages. Same smem.
#define ROWB      144                  // smem row stride bytes (64 f16 + pad)
#define MAT_BYTES (128 * ROWB)         // 18432
#define SMEM_GEMM (12 * MAT_BYTES)     // 221184

// ---------------------------------------------------------------- scratch
static __device__ float   g_S  [(size_t)NTOT*NTOT];            // 256 MB
static __device__ __half  g_ch [(size_t)NTOT*CDIM],  g_cl [(size_t)NTOT*CDIM];
static __device__ __half  g_wqTh[(size_t)CDIM*HD],   g_wqTl[(size_t)CDIM*HD];
static __device__ __half  g_wkTh[(size_t)CDIM*HD],   g_wkTl[(size_t)CDIM*HD];
static __device__ __half  g_mwth[(size_t)HD*CDIM],   g_mwtl[(size_t)HD*CDIM];
static __device__ __half  g_zh [(size_t)NTOT*HD],    g_zl [(size_t)NTOT*HD];
static __device__ __half  g_wpsh[(size_t)HD*HD],     g_wpsl[(size_t)HD*HD];
static __device__ __half  g_wpqh[(size_t)HD*HD],     g_wpql[(size_t)HD*HD];
static __device__ __half  g_pcqh[(size_t)BSQ*BSQ];             // P quadrants, f16
static __device__ __half  g_pqch[(size_t)BSQ*BSQ];
static __device__ __half  g_qTh[(size_t)CDIM*BSQ],   g_qTl[(size_t)CDIM*BSQ];
static __device__ __half  g_sTh[(size_t)CDIM*BSQ],   g_sTl[(size_t)CDIM*BSQ];
static __device__ __half  g_t0h[(size_t)BSQ*HD];               // t, f16
static __device__ __half  g_t1h[(size_t)BSQ*HD];

// ---------------------------------------------------------------- helpers
__device__ __forceinline__ uint32_t smem_u32(const void* p) {
    uint32_t a;
    asm("{ .reg .u64 t; cvta.to.shared.u64 t, %1; cvt.u32.u64 %0, t; }" : "=r"(a) : "l"(p));
    return a;
}
__device__ __forceinline__ void cp16(uint32_t dst, const void* src) {
    asm volatile("cp.async.cg.shared.global [%0], [%1], 16;" :: "r"(dst), "l"(src) : "memory");
}
#define CP_COMMIT() asm volatile("cp.async.commit_group;" ::: "memory")

#define LDSM4(r, a) \
    asm volatile("ldmatrix.sync.aligned.m8n8.x4.shared.b16 {%0,%1,%2,%3}, [%4];" \
        : "=r"((r)[0]), "=r"((r)[1]), "=r"((r)[2]), "=r"((r)[3]) : "r"(a))

#define MMA(d, a, b0, b1) \
    asm volatile("mma.sync.aligned.m16n8k16.row.col.f32.f16.f16.f32 " \
        "{%0,%1,%2,%3}, {%4,%5,%6,%7}, {%8,%9}, {%0,%1,%2,%3};" \
        : "+f"((d)[0]), "+f"((d)[1]), "+f"((d)[2]), "+f"((d)[3]) \
        : "r"((a)[0]), "r"((a)[1]), "r"((a)[2]), "r"((a)[3]), "r"(b0), "r"(b1))

__device__ __forceinline__ unsigned pack2(__half a, __half b) {
    unsigned short x = *reinterpret_cast<unsigned short*>(&a);
    unsigned short y = *reinterpret_cast<unsigned short*>(&b);
    return (unsigned)x | ((unsigned)y << 16);
}
__device__ __forceinline__ void wr_hl4(__half* H, __half* L, size_t off, float4 v) {
    __half h0 = __float2half(v.x), h1 = __float2half(v.y);
    __half h2 = __float2half(v.z), h3 = __float2half(v.w);
    uint2 hu; hu.x = pack2(h0, h1); hu.y = pack2(h2, h3);
    uint2 lu;
    lu.x = pack2(__float2half(v.x - __half2float(h0)),
                 __float2half(v.y - __half2float(h1)));
    lu.y = pack2(__float2half(v.z - __half2float(h2)),
                 __float2half(v.w - __half2float(h3)));
    *reinterpret_cast<uint2*>(H + off) = hu;
    *reinterpret_cast<uint2*>(L + off) = lu;
}

// ---------------------------------------------------------------- HMMA GEMM
// NPROD==3: D = alpha*(Ah@Bh^T + Ah@Bl^T + Al@Bh^T)   (~2^-23 eff. precision)
// NPROD==2: D = alpha*(Ah@Bh^T + Ah@Bl^T)             (A rounded to f16, ~2^-12)
// A: [M][K] row-major f16 (ldA), B: [N][K] row-major f16 (ldB).
// Out: Cf (f32) if non-null, else Ch (+ Cl when non-null) f16.
// K % 64 == 0, K >= 64*(NST-1).
template <int NPROD>
__global__ __launch_bounds__(256, 1) void hmma_gemm(
    const __half* __restrict__ Ah, const __half* __restrict__ Al, size_t ldA,
    const __half* __restrict__ Bh, const __half* __restrict__ Bl, size_t ldB,
    int K, float alpha,
    float* __restrict__ Cf, __half* __restrict__ Ch, __half* __restrict__ Cl,
    int ldc)
{
    constexpr int NMAT = (NPROD == 3) ? 4 : 3;
    constexpr int NST  = (NPROD == 3) ? 3 : 4;
    constexpr int STG  = NMAT * MAT_BYTES;
    constexpr int BOFF = (NPROD == 3) ? 2 * MAT_BYTES : MAT_BYTES;  // B_h offset in stage

    extern __shared__ char dynsm[];
    const uint32_t sbase = smem_u32(dynsm);

    const int tid  = threadIdx.x;
    const int wid  = tid >> 5;
    const int lane = tid & 31;
    const int mBase = blockIdx.y * 128;
    const int nBase = blockIdx.x * 128;
    const int nch = K >> 6;

    const int wm = wid & 3, wn = wid >> 2;

    // ---- load geometry: sel 0..3 -> Ah,Al,Bh,Bl; 2 rows/thread, 8 cp16/row
    const int sel  = tid >> 6;
    const int lrow = (tid & 63) * 2;
    const __half* gsrc;
    size_t gld;
    if (sel == 0)      { gsrc = Ah + (size_t)(mBase + lrow) * ldA; gld = ldA; }
    else if (sel == 1) { gsrc = Al ? Al + (size_t)(mBase + lrow) * ldA : Ah; gld = ldA; }
    else if (sel == 2) { gsrc = Bh + (size_t)(nBase + lrow) * ldB; gld = ldB; }
    else               { gsrc = Bl + (size_t)(nBase + lrow) * ldB; gld = ldB; }
    // stage-local matrix slot: 3-prod keeps 0..3; 2-prod packs Ah,Bh,Bl -> 0,1,2
    const int dsel = (NPROD == 3) ? sel : (sel == 0 ? 0 : (sel == 2 ? 1 : 2));
    const uint32_t sdst0 = sbase + dsel * MAT_BYTES + lrow * ROWB;
    const bool do_load = (NPROD == 3) || (sel != 1);

    #define LOAD_CHUNK(stg, k0) do {                                    \
        if (do_load) {                                                   \
            const uint32_t _d = sdst0 + (stg) * STG;                     \
            const __half* _s = gsrc + (k0);                              \
            _Pragma("unroll")                                            \
            for (int _j = 0; _j < 8; ++_j) {                             \
                cp16(_d + _j * 16,        _s + _j * 8);                  \
                cp16(_d + ROWB + _j * 16, _s + gld + _j * 8);            \
            }                                                            \
        }                                                                \
    } while (0)

    const int l15 = lane & 15;
    const int lc8 = (lane >> 4) << 3;

    float acc[2][8][4];
    #pragma unroll
    for (int i = 0; i < 2; ++i)
        #pragma unroll
        for (int j = 0; j < 8; ++j)
            #pragma unroll
            for (int q = 0; q < 4; ++q) acc[i][j][q] = 0.0f;

    // prologue: NST-1 chunks in flight
    #pragma unroll
    for (int j = 0; j < NST - 1; ++j) {
        LOAD_CHUNK(j, j << 6);
        CP_COMMIT();
    }

    for (int i = 0; i < nch; ++i) {
        asm volatile("cp.async.wait_group %0;" :: "n"(NST - 2) : "memory");
        __syncthreads();
        if (i + NST - 1 < nch) { LOAD_CHUNK((i + NST - 1) % NST, (i + NST - 1) << 6); }
        CP_COMMIT();

        const uint32_t stg = sbase + (i % NST) * STG;
        #pragma unroll
        for (int kk = 0; kk < 64; kk += 16) {
            uint32_t ah[2][4], al[2][4], bh[4][4], bl[4][4];
            #pragma unroll
            for (int mi = 0; mi < 2; ++mi) {
                const uint32_t ao = stg + (wm*32 + mi*16 + l15) * ROWB + (kk + lc8) * 2;
                LDSM4(ah[mi], ao);
                if (NPROD == 3) LDSM4(al[mi], ao + MAT_BYTES);
            }
            #pragma unroll
            for (int g = 0; g < 4; ++g) {
                const uint32_t bo = stg + BOFF + (wn*64 + g*16 + l15) * ROWB + (kk + lc8) * 2;
                LDSM4(bh[g], bo);
                LDSM4(bl[g], bo + MAT_BYTES);
            }
            // product-major: dependent MMAs on same acc are 16 apart
            #pragma unroll
            for (int mi = 0; mi < 2; ++mi)
                #pragma unroll
                for (int g = 0; g < 4; ++g) {
                    MMA(acc[mi][2*g+0], ah[mi], bh[g][0], bh[g][2]);
                    MMA(acc[mi][2*g+1], ah[mi], bh[g][1], bh[g][3]);
                }
            #pragma unroll
            for (int mi = 0; mi < 2; ++mi)
                #pragma unroll
                for (int g = 0; g < 4; ++g) {
                    MMA(acc[mi][2*g+0], ah[mi], bl[g][0], bl[g][2]);
                    MMA(acc[mi][2*g+1], ah[mi], bl[g][1], bl[g][3]);
                }
            if (NPROD == 3) {
                #pragma unroll
                for (int mi = 0; mi < 2; ++mi)
                    #pragma unroll
                    for (int g = 0; g < 4; ++g) {
                        MMA(acc[mi][2*g+0], al[mi], bh[g][0], bh[g][2]);
                        MMA(acc[mi][2*g+1], al[mi], bh[g][1], bh[g][3]);
                    }
            }
        }
    }

    // ---- epilogue
    const int g4 = lane >> 2, t4 = lane & 3;
    #pragma unroll
    for (int mi = 0; mi < 2; ++mi) {
        #pragma unroll
        for (int nj = 0; nj < 8; ++nj) {
            const int r0 = mBase + wm*32 + mi*16 + g4;
            const int c0 = nBase + wn*64 + nj*8 + t4*2;
            float v0 = acc[mi][nj][0] * alpha, v1 = acc[mi][nj][1] * alpha;
            float v2 = acc[mi][nj][2] * alpha, v3 = acc[mi][nj][3] * alpha;
            if (Cf) {
                *reinterpret_cast<float2*>(Cf + (size_t)r0 * ldc + c0)       = make_float2(v0, v1);
                *reinterpret_cast<float2*>(Cf + (size_t)(r0+8) * ldc + c0)   = make_float2(v2, v3);
            } else {
                __half h0 = __float2half(v0), h1 = __float2half(v1);
                __half h2 = __float2half(v2), h3 = __float2half(v3);
                *reinterpret_cast<unsigned*>(Ch + (size_t)r0 * ldc + c0)     = pack2(h0, h1);
                *reinterpret_cast<unsigned*>(Ch + (size_t)(r0+8) * ldc + c0) = pack2(h2, h3);
                if (Cl) {
                    *reinterpret_cast<unsigned*>(Cl + (size_t)r0 * ldc + c0) =
                        pack2(__float2half(v0 - __half2float(h0)),
                              __float2half(v1 - __half2float(h1)));
                    *reinterpret_cast<unsigned*>(Cl + (size_t)(r0+8) * ldc + c0) =
                        pack2(__float2half(v2 - __half2float(h2)),
                              __float2half(v3 - __half2float(h3)));
                }
            }
        }
    }
}

// ---------------------------------------------------------------- small kernels
__global__ __launch_bounds__(256) void build_c_split(const float4* __restrict__ s,
                                                     const float4* __restrict__ tg,
                                                     const float4* __restrict__ q)
{
    const size_t i = (size_t)blockIdx.x * blockDim.x + threadIdx.x;
    float4 a = s[i], b = tg[i];
    float4 r; r.x = a.x + b.x; r.y = a.y + b.y; r.z = a.z + b.z; r.w = a.w + b.w;
    wr_hl4(g_ch, g_cl, i * 4, r);
    float4 qq = q[i];
    wr_hl4(g_ch, g_cl, (size_t)BSQ * CDIM + i * 4, qq);
}

__global__ __launch_bounds__(256) void cvt_w(const float4* __restrict__ w,
                                             __half* __restrict__ H,
                                             __half* __restrict__ L)
{
    const size_t i = (size_t)blockIdx.x * blockDim.x + threadIdx.x;
    wr_hl4(H, L, i * 4, w[i]);
}

// transpose fp32 [R x C] -> f16 hi/lo [C x R]
__global__ __launch_bounds__(256) void transpose_cvt(const float* __restrict__ in,
                                                     __half* __restrict__ oh,
                                                     __half* __restrict__ ol,
                                                     int R, int C)
{
    __shared__ float t[32][33];
    const int tx = threadIdx.x, ty = threadIdx.y;
    const int x = blockIdx.x * 32 + tx;
    #pragma unroll
    for (int j = 0; j < 4; ++j) {
        const int y = blockIdx.y * 32 + ty + j * 8;
        t[ty + j*8][tx] = in[(size_t)y * C + x];
    }
    __syncthreads();
    const int ox = blockIdx.y * 32 + tx;
    #pragma unroll
    for (int j = 0; j < 4; ++j) {
        const int oy = blockIdx.x * 32 + ty + j * 8;
        float v = t[tx][ty + j*8];
        __half h = __float2half(v);
        oh[(size_t)oy * R + ox] = h;
        ol[(size_t)oy * R + ox] = __float2half(v - __half2float(h));
    }
}

// softmax over 8192-wide rows; emit needed quadrant as f16 (hi only)
__global__ __launch_bounds__(512) void softmax_fused(const float* __restrict__ S)
{
    const float* p = S + (size_t)blockIdx.x * NTOT;
    const int t = threadIdx.x;
    float v[16];
    float m = -1e30f;
    #pragma unroll
    for (int i = 0; i < 16; ++i) { v[i] = p[t + i * 512]; m = fmaxf(m, v[i]); }

    __shared__ float red[16];
    #pragma unroll
    for (int o = 16; o; o >>= 1) m = fmaxf(m, __shfl_xor_sync(0xffffffffu, m, o));
    if ((t & 31) == 0) red[t >> 5] = m;
    __syncthreads();
    float mm = red[0];
    #pragma unroll
    for (int i = 1; i < 16; ++i) mm = fmaxf(mm, red[i]);

    float sum = 0.0f;
    #pragma unroll
    for (int i = 0; i < 16; ++i) { v[i] = __expf(v[i] - mm); sum += v[i]; }
    #pragma unroll
    for (int o = 16; o; o >>= 1) sum += __shfl_xor_sync(0xffffffffu, sum, o);
    __syncthreads();
    if ((t & 31) == 0) red[t >> 5] = sum;
    __syncthreads();
    float tot = 0.0f;
    #pragma unroll
    for (int i = 0; i < 16; ++i) tot += red[i];
    const float rcp = 1.0f / tot;

    if (blockIdx.x < BSQ) {
        const size_t rb = (size_t)blockIdx.x * BSQ;
        #pragma unroll
        for (int i = 8; i < 16; ++i) {
            const int col = t + (i - 8) * 512;
            g_pcqh[rb + col] = __float2half(v[i] * rcp);
        }
    } else {
        const size_t rb = (size_t)(blockIdx.x - BSQ) * BSQ;
        #pragma unroll
        for (int i = 0; i < 8; ++i) {
            const int col = t + i * 512;
            g_pqch[rb + col] = __float2half(v[i] * rcp);
        }
    }
}

// ---------------------------------------------------------------- host
static void run_gemm(const __half* Ah, const __half* Al, size_t ldA,
                     const __half* Bh, const __half* Bl, size_t ldB,
                     int M, int N, int K, float alpha,
                     float* Cf, __half* Ch, __half* Cl, int ldc,
                     bool two_prod = false)
{
    if (two_prod)
        hmma_gemm<2><<<dim3(N / 128, M / 128), 256, SMEM_GEMM>>>(
            Ah, Al, ldA, Bh, Bl, ldB, K, alpha, Cf, Ch, Cl, ldc);
    else
        hmma_gemm<3><<<dim3(N / 128, M / 128), 256, SMEM_GEMM>>>(
            Ah, Al, ldA, Bh, Bl, ldB, K, alpha, Cf, Ch, Cl, ldc);
}

extern "C" void kernel_launch(void* const* d_in, const int* in_sizes, int n_in,
                              void* d_out, int out_size)
{
    const float* query = (const float*)d_in[0];
    const float* s     = (const float*)d_in[1];
    const float* tg    = (const float*)d_in[2];
    const float* Wqkv  = (const float*)d_in[3];
    const float* Wps   = (const float*)d_in[4];
    const float* Wpq   = (const float*)d_in[5];
    float* out = (float*)d_out;

    void* p;
    cudaGetSymbolAddress(&p, g_S);    float* S = (float*)p;
    cudaGetSymbolAddress(&p, g_ch);   __half* ch = (__half*)p;
    cudaGetSymbolAddress(&p, g_cl);   __half* cl = (__half*)p;
    cudaGetSymbolAddress(&p, g_wqTh); __half* wqTh = (__half*)p;
    cudaGetSymbolAddress(&p, g_wqTl); __half* wqTl = (__half*)p;
    cudaGetSymbolAddress(&p, g_wkTh); __half* wkTh = (__half*)p;
    cudaGetSymbolAddress(&p, g_wkTl); __half* wkTl = (__half*)p;
    cudaGetSymbolAddress(&p, g_mwth); __half* mwth = (__half*)p;
    cudaGetSymbolAddress(&p, g_mwtl); __half* mwtl = (__half*)p;
    cudaGetSymbolAddress(&p, g_zh);   __half* zh = (__half*)p;
    cudaGetSymbolAddress(&p, g_zl);   __half* zl = (__half*)p;
    cudaGetSymbolAddress(&p, g_wpsh); __half* wpsh = (__half*)p;
    cudaGetSymbolAddress(&p, g_wpsl); __half* wpsl = (__half*)p;
    cudaGetSymbolAddress(&p, g_wpqh); __half* wpqh = (__half*)p;
    cudaGetSymbolAddress(&p, g_wpql); __half* wpql = (__half*)p;
    cudaGetSymbolAddress(&p, g_pcqh); __half* pcqh = (__half*)p;
    cudaGetSymbolAddress(&p, g_pqch); __half* pqch = (__half*)p;
    cudaGetSymbolAddress(&p, g_qTh);  __half* qTh = (__half*)p;
    cudaGetSymbolAddress(&p, g_qTl);  __half* qTl = (__half*)p;
    cudaGetSymbolAddress(&p, g_sTh);  __half* sTh = (__half*)p;
    cudaGetSymbolAddress(&p, g_sTl);  __half* sTl = (__half*)p;
    cudaGetSymbolAddress(&p, g_t0h);  __half* t0h = (__half*)p;
    cudaGetSymbolAddress(&p, g_t1h);  __half* t1h = (__half*)p;

    cudaFuncSetAttribute(hmma_gemm<3>, cudaFuncAttributeMaxDynamicSharedMemorySize, SMEM_GEMM);
    cudaFuncSetAttribute(hmma_gemm<2>, cudaFuncAttributeMaxDynamicSharedMemorySize, SMEM_GEMM);

    // 1) c = [s+TG ; query] -> f16 hi/lo
    build_c_split<<<(BSQ * CDIM / 4) / 256, 256>>>(
        (const float4*)s, (const float4*)tg, (const float4*)query);

    // 2) projection weight conversions
    cvt_w<<<(HD * HD / 4) / 256, 256>>>((const float4*)Wps, wpsh, wpsl);
    cvt_w<<<(HD * HD / 4) / 256, 256>>>((const float4*)Wpq, wpqh, wpql);

    // 3) transposes: query^T, s^T (attn@V B operands), Wq^T, Wk^T
    transpose_cvt<<<dim3(CDIM / 32, BSQ / 32), dim3(32, 8)>>>(query, qTh, qTl, BSQ, CDIM);
    transpose_cvt<<<dim3(CDIM / 32, BSQ / 32), dim3(32, 8)>>>(s, sTh, sTl, BSQ, CDIM);
    transpose_cvt<<<dim3(CDIM / 32, HD / 32), dim3(32, 8)>>>(Wqkv, wqTh, wqTl, HD, CDIM);
    transpose_cvt<<<dim3(CDIM / 32, HD / 32), dim3(32, 8)>>>(Wqkv + (size_t)HD * CDIM,
                                                             wkTh, wkTl, HD, CDIM);

    // 4) MwT = SCALE^2 * Wk^T @ Wq  -> f16 hi/lo [1024 x 1024]  (3-prod)
    run_gemm(wkTh, wkTl, HD, wqTh, wqTl, HD,
             CDIM, CDIM, HD, SCALE2_F, nullptr, mwth, mwtl, CDIM);

    // 5) Z = c @ MwT^T  -> f16 hi/lo [8192 x 1024]  (3-prod, logit path)
    run_gemm(ch, cl, CDIM, mwth, mwtl, CDIM,
             NTOT, HD, CDIM, 1.0f, nullptr, zh, zl, HD);

    // 6) S = Z @ c^T (f32) [8192 x 8192] — 2-prod (Z rounded to f16)
    run_gemm(zh, nullptr, HD, ch, cl, CDIM,
             NTOT, NTOT, HD, 1.0f, S, nullptr, nullptr, NTOT, /*two_prod=*/true);

    // 7) softmax + quadrant split -> f16 (hi only)
    softmax_fused<<<NTOT, 512>>>(S);

    // 8) t0 = Pcq @ query ; t1 = Pqc @ s  -> f16 [4096 x 1024] — 2-prod (P f16)
    run_gemm(pcqh, nullptr, BSQ, qTh, qTl, BSQ,
             BSQ, HD, BSQ, 1.0f, nullptr, t0h, nullptr, HD, /*two_prod=*/true);
    run_gemm(pqch, nullptr, BSQ, sTh, sTl, BSQ,
             BSQ, HD, BSQ, 1.0f, nullptr, t1h, nullptr, HD, /*two_prod=*/true);

    // 9) x_s = t0 @ Wps^T ; x_q = t1 @ Wpq^T (f32 out) — 2-prod (t f16)
    run_gemm(t0h, nullptr, HD, wpsh, wpsl, HD,
             BSQ, HD, HD, 1.0f, out, nullptr, nullptr, HD, /*two_prod=*/true);
    run_gemm(t1h, nullptr, HD, wpqh, wpql, HD,
             BSQ, HD, HD, 1.0f, out + (size_t)BSQ * HD, nullptr, nullptr, HD, /*two_prod=*/true);
}

// round 12
// speedup vs baseline: 1.7498x; 1.1291x over previous
#include <cuda_runtime.h>
#include <cuda_fp16.h>
#include <cstdint>
#include <math.h>

// ---------------------------------------------------------------- constants
#define BSQ   4096
#define CDIM  1024
#define NTOT  8192
#define HD    1024
#define SCALE2_F 0.03125f              // (1024^-0.25)^2 = 1/32

// GEMM config: CTA 128x128, k-chunk 64
// 3-prod: 4 mats/stage x3 stages. 2-prod: 3x4. 1-prod: 2x6. Same smem.
#define ROWB      144                  // smem row stride bytes (64 f16 + pad)
#define MAT_BYTES (128 * ROWB)         // 18432
#define SMEM_GEMM (12 * MAT_BYTES)     // 221184

// ---------------------------------------------------------------- scratch
static __device__ float   g_S  [(size_t)NTOT*NTOT];            // 256 MB
static __device__ __half  g_ch [(size_t)NTOT*CDIM],  g_cl [(size_t)NTOT*CDIM];
static __device__ __half  g_wqTh[(size_t)CDIM*HD],   g_wqTl[(size_t)CDIM*HD];
static __device__ __half  g_wkTh[(size_t)CDIM*HD],   g_wkTl[(size_t)CDIM*HD];
static __device__ __half  g_mwth[(size_t)HD*CDIM],   g_mwtl[(size_t)HD*CDIM];
static __device__ __half  g_zh [(size_t)NTOT*HD],    g_zl [(size_t)NTOT*HD];
static __device__ __half  g_wpsh[(size_t)HD*HD],     g_wpsl[(size_t)HD*HD];
static __device__ __half  g_wpqh[(size_t)HD*HD],     g_wpql[(size_t)HD*HD];
static __device__ __half  g_pcqh[(size_t)BSQ*BSQ];             // P quadrants, f16
static __device__ __half  g_pqch[(size_t)BSQ*BSQ];
static __device__ __half  g_qTh[(size_t)CDIM*BSQ];             // query^T, s^T f16 (hi only)
static __device__ __half  g_sTh[(size_t)CDIM*BSQ];
static __device__ __half  g_t0h[(size_t)BSQ*HD];               // t, f16
static __device__ __half  g_t1h[(size_t)BSQ*HD];

// ---------------------------------------------------------------- helpers
__device__ __forceinline__ uint32_t smem_u32(const void* p) {
    uint32_t a;
    asm("{ .reg .u64 t; cvta.to.shared.u64 t, %1; cvt.u32.u64 %0, t; }" : "=r"(a) : "l"(p));
    return a;
}
__device__ __forceinline__ void cp16(uint32_t dst, const void* src) {
    asm volatile("cp.async.cg.shared.global [%0], [%1], 16;" :: "r"(dst), "l"(src) : "memory");
}
#define CP_COMMIT() asm volatile("cp.async.commit_group;" ::: "memory")

#define LDSM4(r, a) \
    asm volatile("ldmatrix.sync.aligned.m8n8.x4.shared.b16 {%0,%1,%2,%3}, [%4];" \
        : "=r"((r)[0]), "=r"((r)[1]), "=r"((r)[2]), "=r"((r)[3]) : "r"(a))

#define MMA(d, a, b0, b1) \
    asm volatile("mma.sync.aligned.m16n8k16.row.col.f32.f16.f16.f32 " \
        "{%0,%1,%2,%3}, {%4,%5,%6,%7}, {%8,%9}, {%0,%1,%2,%3};" \
        : "+f"((d)[0]), "+f"((d)[1]), "+f"((d)[2]), "+f"((d)[3]) \
        : "r"((a)[0]), "r"((a)[1]), "r"((a)[2]), "r"((a)[3]), "r"(b0), "r"(b1))

__device__ __forceinline__ unsigned pack2(__half a, __half b) {
    unsigned short x = *reinterpret_cast<unsigned short*>(&a);
    unsigned short y = *reinterpret_cast<unsigned short*>(&b);
    return (unsigned)x | ((unsigned)y << 16);
}
__device__ __forceinline__ void wr_hl4(__half* H, __half* L, size_t off, float4 v) {
    __half h0 = __float2half(v.x), h1 = __float2half(v.y);
    __half h2 = __float2half(v.z), h3 = __float2half(v.w);
    uint2 hu; hu.x = pack2(h0, h1); hu.y = pack2(h2, h3);
    uint2 lu;
    lu.x = pack2(__float2half(v.x - __half2float(h0)),
                 __float2half(v.y - __half2float(h1)));
    lu.y = pack2(__float2half(v.z - __half2float(h2)),
                 __float2half(v.w - __half2float(h3)));
    *reinterpret_cast<uint2*>(H + off) = hu;
    *reinterpret_cast<uint2*>(L + off) = lu;
}

// ---------------------------------------------------------------- HMMA GEMM
// NPROD==3: D = alpha*(Ah@Bh^T + Ah@Bl^T + Al@Bh^T)   (~2^-23 eff.)
// NPROD==2: D = alpha*(Ah@Bh^T + Ah@Bl^T)             (A rounded, ~2^-12)
// NPROD==1: D = alpha*(Ah@Bh^T)                       (both rounded, ~2^-12 each)
// A: [M][K] row-major f16 (ldA), B: [N][K] row-major f16 (ldB).
// Out: Cf (f32) if non-null, else Ch (+ Cl when non-null) f16.
// K % 64 == 0, K >= 64*(NST-1).
template <int NPROD>
__global__ __launch_bounds__(256, 1) void hmma_gemm(
    const __half* __restrict__ Ah, const __half* __restrict__ Al, size_t ldA,
    const __half* __restrict__ Bh, const __half* __restrict__ Bl, size_t ldB,
    int K, float alpha,
    float* __restrict__ Cf, __half* __restrict__ Ch, __half* __restrict__ Cl,
    int ldc)
{
    constexpr int NMAT = (NPROD == 3) ? 4 : (NPROD == 2 ? 3 : 2);
    constexpr int NST  = 12 / NMAT;                   // 3, 4, 6
    constexpr int STG  = NMAT * MAT_BYTES;
    constexpr int BOFF = (NPROD == 3) ? 2 * MAT_BYTES : MAT_BYTES;

    extern __shared__ char dynsm[];
    const uint32_t sbase = smem_u32(dynsm);

    const int tid  = threadIdx.x;
    const int wid  = tid >> 5;
    const int lane = tid & 31;
    const int mBase = blockIdx.y * 128;
    const int nBase = blockIdx.x * 128;
    const int nch = K >> 6;

    const int wm = wid & 3, wn = wid >> 2;

    // ---- load geometry
    const __half* gsrc;
    size_t gld = 0;
    uint32_t sdst0;
    bool do_load = true;
    bool two_rows;
    if (NPROD == 1) {
        // 2 matrices, 256 threads: 1 row/thread, 8 cp16 per chunk
        const int mat = tid >> 7;            // 0: Ah, 1: Bh
        const int row = tid & 127;
        gsrc = (mat == 0) ? Ah + (size_t)(mBase + row) * ldA
                          : Bh + (size_t)(nBase + row) * ldB;
        sdst0 = sbase + mat * MAT_BYTES + row * ROWB;
        two_rows = false;
    } else {
        // 4 groups of 64 threads: 2 rows/thread, 16 cp16 per chunk
        const int sel  = tid >> 6;
        const int lrow = (tid & 63) * 2;
        if (sel == 0)      { gsrc = Ah + (size_t)(mBase + lrow) * ldA; gld = ldA; }
        else if (sel == 1) { gsrc = Al ? Al + (size_t)(mBase + lrow) * ldA : Ah; gld = ldA; }
        else if (sel == 2) { gsrc = Bh + (size_t)(nBase + lrow) * ldB; gld = ldB; }
        else               { gsrc = Bl + (size_t)(nBase + lrow) * ldB; gld = ldB; }
        const int dsel = (NPROD == 3) ? sel : (sel == 0 ? 0 : (sel == 2 ? 1 : 2));
        sdst0 = sbase + dsel * MAT_BYTES + lrow * ROWB;
        do_load = (NPROD == 3) || (sel != 1);
        two_rows = true;
    }

    #define LOAD_CHUNK(stg, k0) do {                                    \
        if (do_load) {                                                   \
            const uint32_t _d = sdst0 + (stg) * STG;                     \
            const __half* _s = gsrc + (k0);                              \
            _Pragma("unroll")                                            \
            for (int _j = 0; _j < 8; ++_j) {                             \
                cp16(_d + _j * 16, _s + _j * 8);                         \
                if (two_rows) cp16(_d + ROWB + _j * 16, _s + gld + _j * 8); \
            }                                                            \
        }                                                                \
    } while (0)

    const int l15 = lane & 15;
    const int lc8 = (lane >> 4) << 3;

    float acc[2][8][4];
    #pragma unroll
    for (int i = 0; i < 2; ++i)
        #pragma unroll
        for (int j = 0; j < 8; ++j)
            #pragma unroll
            for (int q = 0; q < 4; ++q) acc[i][j][q] = 0.0f;

    // prologue: NST-1 chunks in flight
    #pragma unroll
    for (int j = 0; j < NST - 1; ++j) {
        LOAD_CHUNK(j, j << 6);
        CP_COMMIT();
    }

    for (int i = 0; i < nch; ++i) {
        asm volatile("cp.async.wait_group %0;" :: "n"(NST - 2) : "memory");
        __syncthreads();
        if (i + NST - 1 < nch) { LOAD_CHUNK((i + NST - 1) % NST, (i + NST - 1) << 6); }
        CP_COMMIT();

        const uint32_t stg = sbase + (i % NST) * STG;
        #pragma unroll
        for (int kk = 0; kk < 64; kk += 16) {
            uint32_t ah[2][4], al[2][4], bh[4][4], bl[4][4];
            #pragma unroll
            for (int mi = 0; mi < 2; ++mi) {
                const uint32_t ao = stg + (wm*32 + mi*16 + l15) * ROWB + (kk + lc8) * 2;
                LDSM4(ah[mi], ao);
                if (NPROD == 3) LDSM4(al[mi], ao + MAT_BYTES);
            }
            #pragma unroll
            for (int g = 0; g < 4; ++g) {
                const uint32_t bo = stg + BOFF + (wn*64 + g*16 + l15) * ROWB + (kk + lc8) * 2;
                LDSM4(bh[g], bo);
                if (NPROD >= 2) LDSM4(bl[g], bo + MAT_BYTES);
            }
            // product-major: dependent MMAs on same acc are 16 apart
            #pragma unroll
            for (int mi = 0; mi < 2; ++mi)
                #pragma unroll
                for (int g = 0; g < 4; ++g) {
                    MMA(acc[mi][2*g+0], ah[mi], bh[g][0], bh[g][2]);
                    MMA(acc[mi][2*g+1], ah[mi], bh[g][1], bh[g][3]);
                }
            if (NPROD >= 2) {
                #pragma unroll
                for (int mi = 0; mi < 2; ++mi)
                    #pragma unroll
                    for (int g = 0; g < 4; ++g) {
                        MMA(acc[mi][2*g+0], ah[mi], bl[g][0], bl[g][2]);
                        MMA(acc[mi][2*g+1], ah[mi], bl[g][1], bl[g][3]);
                    }
            }
            if (NPROD == 3) {
                #pragma unroll
                for (int mi = 0; mi < 2; ++mi)
                    #pragma unroll
                    for (int g = 0; g < 4; ++g) {
                        MMA(acc[mi][2*g+0], al[mi], bh[g][0], bh[g][2]);
                        MMA(acc[mi][2*g+1], al[mi], bh[g][1], bh[g][3]);
                    }
            }
        }
    }

    // ---- epilogue
    const int g4 = lane >> 2, t4 = lane & 3;
    #pragma unroll
    for (int mi = 0; mi < 2; ++mi) {
        #pragma unroll
        for (int nj = 0; nj < 8; ++nj) {
            const int r0 = mBase + wm*32 + mi*16 + g4;
            const int c0 = nBase + wn*64 + nj*8 + t4*2;
            float v0 = acc[mi][nj][0] * alpha, v1 = acc[mi][nj][1] * alpha;
            float v2 = acc[mi][nj][2] * alpha, v3 = acc[mi][nj][3] * alpha;
            if (Cf) {
                *reinterpret_cast<float2*>(Cf + (size_t)r0 * ldc + c0)       = make_float2(v0, v1);
                *reinterpret_cast<float2*>(Cf + (size_t)(r0+8) * ldc + c0)   = make_float2(v2, v3);
            } else {
                __half h0 = __float2half(v0), h1 = __float2half(v1);
                __half h2 = __float2half(v2), h3 = __float2half(v3);
                *reinterpret_cast<unsigned*>(Ch + (size_t)r0 * ldc + c0)     = pack2(h0, h1);
                *reinterpret_cast<unsigned*>(Ch + (size_t)(r0+8) * ldc + c0) = pack2(h2, h3);
                if (Cl) {
                    *reinterpret_cast<unsigned*>(Cl + (size_t)r0 * ldc + c0) =
                        pack2(__float2half(v0 - __half2float(h0)),
                              __float2half(v1 - __half2float(h1)));
                    *reinterpret_cast<unsigned*>(Cl + (size_t)(r0+8) * ldc + c0) =
                        pack2(__float2half(v2 - __half2float(h2)),
                              __float2half(v3 - __half2float(h3)));
                }
            }
        }
    }
}

// ---------------------------------------------------------------- small kernels
__global__ __launch_bounds__(256) void build_c_split(const float4* __restrict__ s,
                                                     const float4* __restrict__ tg,
                                                     const float4* __restrict__ q)
{
    const size_t i = (size_t)blockIdx.x * blockDim.x + threadIdx.x;
    float4 a = s[i], b = tg[i];
    float4 r; r.x = a.x + b.x; r.y = a.y + b.y; r.z = a.z + b.z; r.w = a.w + b.w;
    wr_hl4(g_ch, g_cl, i * 4, r);
    float4 qq = q[i];
    wr_hl4(g_ch, g_cl, (size_t)BSQ * CDIM + i * 4, qq);
}

__global__ __launch_bounds__(256) void cvt_w(const float4* __restrict__ w,
                                             __half* __restrict__ H,
                                             __half* __restrict__ L)
{
    const size_t i = (size_t)blockIdx.x * blockDim.x + threadIdx.x;
    wr_hl4(H, L, i * 4, w[i]);
}

// transpose fp32 [R x C] -> f16 hi/lo [C x R] (ol may be null)
__global__ __launch_bounds__(256) void transpose_cvt(const float* __restrict__ in,
                                                     __half* __restrict__ oh,
                                                     __half* __restrict__ ol,
                                                     int R, int C)
{
    __shared__ float t[32][33];
    const int tx = threadIdx.x, ty = threadIdx.y;
    const int x = blockIdx.x * 32 + tx;
    #pragma unroll
    for (int j = 0; j < 4; ++j) {
        const int y = blockIdx.y * 32 + ty + j * 8;
        t[ty + j*8][tx] = in[(size_t)y * C + x];
    }
    __syncthreads();
    const int ox = blockIdx.y * 32 + tx;
    #pragma unroll
    for (int j = 0; j < 4; ++j) {
        const int oy = blockIdx.x * 32 + ty + j * 8;
        float v = t[tx][ty + j*8];
        __half h = __float2half(v);
        oh[(size_t)oy * R + ox] = h;
        if (ol) ol[(size_t)oy * R + ox] = __float2half(v - __half2float(h));
    }
}

// softmax over 8192-wide rows; emit needed quadrant as f16 (hi only)
__global__ __launch_bounds__(512) void softmax_fused(const float* __restrict__ S)
{
    const float* p = S + (size_t)blockIdx.x * NTOT;
    const int t = threadIdx.x;
    float v[16];
    float m = -1e30f;
    #pragma unroll
    for (int i = 0; i < 16; ++i) { v[i] = p[t + i * 512]; m = fmaxf(m, v[i]); }

    __shared__ float red[16];
    #pragma unroll
    for (int o = 16; o; o >>= 1) m = fmaxf(m, __shfl_xor_sync(0xffffffffu, m, o));
    if ((t & 31) == 0) red[t >> 5] = m;
    __syncthreads();
    float mm = red[0];
    #pragma unroll
    for (int i = 1; i < 16; ++i) mm = fmaxf(mm, red[i]);

    float sum = 0.0f;
    #pragma unroll
    for (int i = 0; i < 16; ++i) { v[i] = __expf(v[i] - mm); sum += v[i]; }
    #pragma unroll
    for (int o = 16; o; o >>= 1) sum += __shfl_xor_sync(0xffffffffu, sum, o);
    __syncthreads();
    if ((t & 31) == 0) red[t >> 5] = sum;
    __syncthreads();
    float tot = 0.0f;
    #pragma unroll
    for (int i = 0; i < 16; ++i) tot += red[i];
    const float rcp = 1.0f / tot;

    if (blockIdx.x < BSQ) {
        const size_t rb = (size_t)blockIdx.x * BSQ;
        #pragma unroll
        for (int i = 8; i < 16; ++i) {
            const int col = t + (i - 8) * 512;
            g_pcqh[rb + col] = __float2half(v[i] * rcp);
        }
    } else {
        const size_t rb = (size_t)(blockIdx.x - BSQ) * BSQ;
        #pragma unroll
        for (int i = 0; i < 8; ++i) {
            const int col = t + i * 512;
            g_pqch[rb + col] = __float2half(v[i] * rcp);
        }
    }
}

// ---------------------------------------------------------------- host
static void run_gemm(const __half* Ah, const __half* Al, size_t ldA,
                     const __half* Bh, const __half* Bl, size_t ldB,
                     int M, int N, int K, float alpha,
                     float* Cf, __half* Ch, __half* Cl, int ldc,
                     int nprod)
{
    dim3 grid(N / 128, M / 128);
    if (nprod == 1)
        hmma_gemm<1><<<grid, 256, SMEM_GEMM>>>(Ah, Al, ldA, Bh, Bl, ldB, K, alpha, Cf, Ch, Cl, ldc);
    else if (nprod == 2)
        hmma_gemm<2><<<grid, 256, SMEM_GEMM>>>(Ah, Al, ldA, Bh, Bl, ldB, K, alpha, Cf, Ch, Cl, ldc);
    else
        hmma_gemm<3><<<grid, 256, SMEM_GEMM>>>(Ah, Al, ldA, Bh, Bl, ldB, K, alpha, Cf, Ch, Cl, ldc);
}

extern "C" void kernel_launch(void* const* d_in, const int* in_sizes, int n_in,
                              void* d_out, int out_size)
{
    const float* query = (const float*)d_in[0];
    const float* s     = (const float*)d_in[1];
    const float* tg    = (const float*)d_in[2];
    const float* Wqkv  = (const float*)d_in[3];
    const float* Wps   = (const float*)d_in[4];
    const float* Wpq   = (const float*)d_in[5];
    float* out = (float*)d_out;

    void* p;
    cudaGetSymbolAddress(&p, g_S);    float* S = (float*)p;
    cudaGetSymbolAddress(&p, g_ch);   __half* ch = (__half*)p;
    cudaGetSymbolAddress(&p, g_cl);   __half* cl = (__half*)p;
    cudaGetSymbolAddress(&p, g_wqTh); __half* wqTh = (__half*)p;
    cudaGetSymbolAddress(&p, g_wqTl); __half* wqTl = (__half*)p;
    cudaGetSymbolAddress(&p, g_wkTh); __half* wkTh = (__half*)p;
    cudaGetSymbolAddress(&p, g_wkTl); __half* wkTl = (__half*)p;
    cudaGetSymbolAddress(&p, g_mwth); __half* mwth = (__half*)p;
    cudaGetSymbolAddress(&p, g_mwtl); __half* mwtl = (__half*)p;
    cudaGetSymbolAddress(&p, g_zh);   __half* zh = (__half*)p;
    cudaGetSymbolAddress(&p, g_zl);   __half* zl = (__half*)p;
    cudaGetSymbolAddress(&p, g_wpsh); __half* wpsh = (__half*)p;
    cudaGetSymbolAddress(&p, g_wpsl); __half* wpsl = (__half*)p;
    cudaGetSymbolAddress(&p, g_wpqh); __half* wpqh = (__half*)p;
    cudaGetSymbolAddress(&p, g_wpql); __half* wpql = (__half*)p;
    cudaGetSymbolAddress(&p, g_pcqh); __half* pcqh = (__half*)p;
    cudaGetSymbolAddress(&p, g_pqch); __half* pqch = (__half*)p;
    cudaGetSymbolAddress(&p, g_qTh);  __half* qTh = (__half*)p;
    cudaGetSymbolAddress(&p, g_sTh);  __half* sTh = (__half*)p;
    cudaGetSymbolAddress(&p, g_t0h);  __half* t0h = (__half*)p;
    cudaGetSymbolAddress(&p, g_t1h);  __half* t1h = (__half*)p;

    cudaFuncSetAttribute(hmma_gemm<3>, cudaFuncAttributeMaxDynamicSharedMemorySize, SMEM_GEMM);
    cudaFuncSetAttribute(hmma_gemm<2>, cudaFuncAttributeMaxDynamicSharedMemorySize, SMEM_GEMM);
    cudaFuncSetAttribute(hmma_gemm<1>, cudaFuncAttributeMaxDynamicSharedMemorySize, SMEM_GEMM);

    // 1) c = [s+TG ; query] -> f16 hi/lo
    build_c_split<<<(BSQ * CDIM / 4) / 256, 256>>>(
        (const float4*)s, (const float4*)tg, (const float4*)query);

    // 2) projection weight conversions (hi/lo — proj is 2-prod)
    cvt_w<<<(HD * HD / 4) / 256, 256>>>((const float4*)Wps, wpsh, wpsl);
    cvt_w<<<(HD * HD / 4) / 256, 256>>>((const float4*)Wpq, wpqh, wpql);

    // 3) transposes: query^T, s^T hi-only (P@V is 1-prod); Wq^T, Wk^T hi/lo
    transpose_cvt<<<dim3(CDIM / 32, BSQ / 32), dim3(32, 8)>>>(query, qTh, nullptr, BSQ, CDIM);
    transpose_cvt<<<dim3(CDIM / 32, BSQ / 32), dim3(32, 8)>>>(s, sTh, nullptr, BSQ, CDIM);
    transpose_cvt<<<dim3(CDIM / 32, HD / 32), dim3(32, 8)>>>(Wqkv, wqTh, wqTl, HD, CDIM);
    transpose_cvt<<<dim3(CDIM / 32, HD / 32), dim3(32, 8)>>>(Wqkv + (size_t)HD * CDIM,
                                                             wkTh, wkTl, HD, CDIM);

    // 4) MwT = SCALE^2 * Wk^T @ Wq  -> f16 hi/lo [1024 x 1024]  (3-prod)
    run_gemm(wkTh, wkTl, HD, wqTh, wqTl, HD,
             CDIM, CDIM, HD, SCALE2_F, nullptr, mwth, mwtl, CDIM, 3);

    // 5) Z = c @ MwT^T  -> f16 hi/lo [8192 x 1024]  (3-prod, logit path)
    run_gemm(ch, cl, CDIM, mwth, mwtl, CDIM,
             NTOT, HD, CDIM, 1.0f, nullptr, zh, zl, HD, 3);

    // 6) S = Z @ c^T (f32) [8192 x 8192] — 2-prod (Z rounded to f16)
    run_gemm(zh, nullptr, HD, ch, cl, CDIM,
             NTOT, NTOT, HD, 1.0f, S, nullptr, nullptr, NTOT, 2);

    // 7) softmax + quadrant split -> f16 (hi only)
    softmax_fused<<<NTOT, 512>>>(S);

    // 8) t0 = Pcq @ query ; t1 = Pqc @ s — 1-prod (pure f16 hh)
    run_gemm(pcqh, nullptr, BSQ, qTh, nullptr, BSQ,
             BSQ, HD, BSQ, 1.0f, nullptr, t0h, nullptr, HD, 1);
    run_gemm(pqch, nullptr, BSQ, sTh, nullptr, BSQ,
             BSQ, HD, BSQ, 1.0f, nullptr, t1h, nullptr, HD, 1);

    // 9) x_s = t0 @ Wps^T ; x_q = t1 @ Wpq^T (f32 out) — 2-prod (t f16)
    run_gemm(t0h, nullptr, HD, wpsh, wpsl, HD,
             BSQ, HD, HD, 1.0f, out, nullptr, nullptr, HD, 2);
    run_gemm(t1h, nullptr, HD, wpqh, wpql, HD,
             BSQ, HD, HD, 1.0f, out + (size_t)BSQ * HD, nullptr, nullptr, HD, 2);
}

// round 14
// speedup vs baseline: 2.2136x; 1.2650x over previous
#include <cuda_runtime.h>
#include <cuda_fp16.h>
#include <cstdint>
#include <math.h>

// ---------------------------------------------------------------- constants
#define BSQ   4096
#define CDIM  1024
#define NTOT  8192
#define HD    1024
#define SCALE2_F 0.03125f              // (1024^-0.25)^2 = 1/32

// GEMM config: CTA 128x128, k-chunk 64
// 3-prod: 4 mats/stage x3 stages. 2-prod: 3x4. 1-prod: 2x6. Same smem.
#define ROWB      144                  // smem row stride bytes (64 f16 + pad)
#define MAT_BYTES (128 * ROWB)         // 18432
#define SMEM_GEMM (12 * MAT_BYTES)     // 221184

// ---------------------------------------------------------------- scratch
static __device__ float   g_S  [(size_t)NTOT*NTOT];            // 256 MB
static __device__ __half  g_ch [(size_t)NTOT*CDIM],  g_cl [(size_t)NTOT*CDIM];
static __device__ __half  g_wqTh[(size_t)CDIM*HD],   g_wqTl[(size_t)CDIM*HD];
static __device__ __half  g_wkTh[(size_t)CDIM*HD],   g_wkTl[(size_t)CDIM*HD];
static __device__ __half  g_mwth[(size_t)HD*CDIM],   g_mwtl[(size_t)HD*CDIM];
static __device__ __half  g_zh [(size_t)NTOT*HD],    g_zl [(size_t)NTOT*HD];
static __device__ __half  g_wpsh[(size_t)HD*HD],     g_wpsl[(size_t)HD*HD];
static __device__ __half  g_wpqh[(size_t)HD*HD],     g_wpql[(size_t)HD*HD];
static __device__ __half  g_pcqh[(size_t)BSQ*BSQ];             // P quadrants, f16
static __device__ __half  g_pqch[(size_t)BSQ*BSQ];
static __device__ __half  g_qTh[(size_t)CDIM*BSQ];             // query^T, s^T f16 (hi)
static __device__ __half  g_sTh[(size_t)CDIM*BSQ];
static __device__ __half  g_t0h[(size_t)BSQ*HD];               // t, f16
static __device__ __half  g_t1h[(size_t)BSQ*HD];

// ---------------------------------------------------------------- helpers
__device__ __forceinline__ uint32_t smem_u32(const void* p) {
    uint32_t a;
    asm("{ .reg .u64 t; cvta.to.shared.u64 t, %1; cvt.u32.u64 %0, t; }" : "=r"(a) : "l"(p));
    return a;
}
__device__ __forceinline__ void cp16(uint32_t dst, const void* src) {
    asm volatile("cp.async.cg.shared.global [%0], [%1], 16;" :: "r"(dst), "l"(src) : "memory");
}
#define CP_COMMIT() asm volatile("cp.async.commit_group;" ::: "memory")

#define LDSM4(r, a) \
    asm volatile("ldmatrix.sync.aligned.m8n8.x4.shared.b16 {%0,%1,%2,%3}, [%4];" \
        : "=r"((r)[0]), "=r"((r)[1]), "=r"((r)[2]), "=r"((r)[3]) : "r"(a))

#define MMA(d, a, b0, b1) \
    asm volatile("mma.sync.aligned.m16n8k16.row.col.f32.f16.f16.f32 " \
        "{%0,%1,%2,%3}, {%4,%5,%6,%7}, {%8,%9}, {%0,%1,%2,%3};" \
        : "+f"((d)[0]), "+f"((d)[1]), "+f"((d)[2]), "+f"((d)[3]) \
        : "r"((a)[0]), "r"((a)[1]), "r"((a)[2]), "r"((a)[3]), "r"(b0), "r"(b1))

__device__ __forceinline__ unsigned pack2(__half a, __half b) {
    unsigned short x = *reinterpret_cast<unsigned short*>(&a);
    unsigned short y = *reinterpret_cast<unsigned short*>(&b);
    return (unsigned)x | ((unsigned)y << 16);
}
__device__ __forceinline__ void wr_hl4(__half* H, __half* L, size_t off, float4 v) {
    __half h0 = __float2half(v.x), h1 = __float2half(v.y);
    __half h2 = __float2half(v.z), h3 = __float2half(v.w);
    uint2 hu; hu.x = pack2(h0, h1); hu.y = pack2(h2, h3);
    uint2 lu;
    lu.x = pack2(__float2half(v.x - __half2float(h0)),
                 __float2half(v.y - __half2float(h1)));
    lu.y = pack2(__float2half(v.z - __half2float(h2)),
                 __float2half(v.w - __half2float(h3)));
    *reinterpret_cast<uint2*>(H + off) = hu;
    *reinterpret_cast<uint2*>(L + off) = lu;
}

// ---------------------------------------------------------------- HMMA GEMM
// NPROD==3: D = alpha*(Ah@Bh^T + Ah@Bl^T + Al@Bh^T)   (~2^-23 eff.)
// NPROD==2: D = alpha*(Ah@Bh^T + Ah@Bl^T)             (A rounded, ~2^-12)
// NPROD==1: D = alpha*(Ah@Bh^T)                       (both rounded, ~2^-12 each)
// A: [M][K] row-major f16 (ldA), B: [N][K] row-major f16 (ldB).
// Out: Cf (f32) if non-null, else Ch (+ Cl when non-null) f16.
// K % 64 == 0, K >= 64*(NST-1).
template <int NPROD>
__global__ __launch_bounds__(256, 1) void hmma_gemm(
    const __half* __restrict__ Ah, const __half* __restrict__ Al, size_t ldA,
    const __half* __restrict__ Bh, const __half* __restrict__ Bl, size_t ldB,
    int K, float alpha,
    float* __restrict__ Cf, __half* __restrict__ Ch, __half* __restrict__ Cl,
    int ldc)
{
    constexpr int NMAT = (NPROD == 3) ? 4 : (NPROD == 2 ? 3 : 2);
    constexpr int NST  = 12 / NMAT;                   // 3, 4, 6
    constexpr int STG  = NMAT * MAT_BYTES;
    constexpr int BOFF = (NPROD == 3) ? 2 * MAT_BYTES : MAT_BYTES;

    extern __shared__ char dynsm[];
    const uint32_t sbase = smem_u32(dynsm);

    const int tid  = threadIdx.x;
    const int wid  = tid >> 5;
    const int lane = tid & 31;
    const int mBase = blockIdx.y * 128;
    const int nBase = blockIdx.x * 128;
    const int nch = K >> 6;

    const int wm = wid & 3, wn = wid >> 2;

    // ---- load geometry
    const __half* gsrc;
    size_t gld = 0;
    uint32_t sdst0;
    bool do_load = true;
    bool two_rows;
    if (NPROD == 1) {
        const int mat = tid >> 7;            // 0: Ah, 1: Bh
        const int row = tid & 127;
        gsrc = (mat == 0) ? Ah + (size_t)(mBase + row) * ldA
                          : Bh + (size_t)(nBase + row) * ldB;
        sdst0 = sbase + mat * MAT_BYTES + row * ROWB;
        two_rows = false;
    } else {
        const int sel  = tid >> 6;
        const int lrow = (tid & 63) * 2;
        if (sel == 0)      { gsrc = Ah + (size_t)(mBase + lrow) * ldA; gld = ldA; }
        else if (sel == 1) { gsrc = Al ? Al + (size_t)(mBase + lrow) * ldA : Ah; gld = ldA; }
        else if (sel == 2) { gsrc = Bh + (size_t)(nBase + lrow) * ldB; gld = ldB; }
        else               { gsrc = Bl + (size_t)(nBase + lrow) * ldB; gld = ldB; }
        const int dsel = (NPROD == 3) ? sel : (sel == 0 ? 0 : (sel == 2 ? 1 : 2));
        sdst0 = sbase + dsel * MAT_BYTES + lrow * ROWB;
        do_load = (NPROD == 3) || (sel != 1);
        two_rows = true;
    }

    #define LOAD_CHUNK(stg, k0) do {                                    \
        if (do_load) {                                                   \
            const uint32_t _d = sdst0 + (stg) * STG;                     \
            const __half* _s = gsrc + (k0);                              \
            _Pragma("unroll")                                            \
            for (int _j = 0; _j < 8; ++_j) {                             \
                cp16(_d + _j * 16, _s + _j * 8);                         \
                if (two_rows) cp16(_d + ROWB + _j * 16, _s + gld + _j * 8); \
            }                                                            \
        }                                                                \
    } while (0)

    const int l15 = lane & 15;
    const int lc8 = (lane >> 4) << 3;

    float acc[2][8][4];
    #pragma unroll
    for (int i = 0; i < 2; ++i)
        #pragma unroll
        for (int j = 0; j < 8; ++j)
            #pragma unroll
            for (int q = 0; q < 4; ++q) acc[i][j][q] = 0.0f;

    // prologue: NST-1 chunks in flight
    #pragma unroll
    for (int j = 0; j < NST - 1; ++j) {
        LOAD_CHUNK(j, j << 6);
        CP_COMMIT();
    }

    for (int i = 0; i < nch; ++i) {
        asm volatile("cp.async.wait_group %0;" :: "n"(NST - 2) : "memory");
        __syncthreads();
        if (i + NST - 1 < nch) { LOAD_CHUNK((i + NST - 1) % NST, (i + NST - 1) << 6); }
        CP_COMMIT();

        const uint32_t stg = sbase + (i % NST) * STG;
        #pragma unroll
        for (int kk = 0; kk < 64; kk += 16) {
            uint32_t ah[2][4], al[2][4], bh[4][4], bl[4][4];
            #pragma unroll
            for (int mi = 0; mi < 2; ++mi) {
                const uint32_t ao = stg + (wm*32 + mi*16 + l15) * ROWB + (kk + lc8) * 2;
                LDSM4(ah[mi], ao);
                if (NPROD == 3) LDSM4(al[mi], ao + MAT_BYTES);
            }
            #pragma unroll
            for (int g = 0; g < 4; ++g) {
                const uint32_t bo = stg + BOFF + (wn*64 + g*16 + l15) * ROWB + (kk + lc8) * 2;
                LDSM4(bh[g], bo);
                if (NPROD >= 2) LDSM4(bl[g], bo + MAT_BYTES);
            }
            // product-major: dependent MMAs on same acc are 16 apart
            #pragma unroll
            for (int mi = 0; mi < 2; ++mi)
                #pragma unroll
                for (int g = 0; g < 4; ++g) {
                    MMA(acc[mi][2*g+0], ah[mi], bh[g][0], bh[g][2]);
                    MMA(acc[mi][2*g+1], ah[mi], bh[g][1], bh[g][3]);
                }
            if (NPROD >= 2) {
                #pragma unroll
                for (int mi = 0; mi < 2; ++mi)
                    #pragma unroll
                    for (int g = 0; g < 4; ++g) {
                        MMA(acc[mi][2*g+0], ah[mi], bl[g][0], bl[g][2]);
                        MMA(acc[mi][2*g+1], ah[mi], bl[g][1], bl[g][3]);
                    }
            }
            if (NPROD == 3) {
                #pragma unroll
                for (int mi = 0; mi < 2; ++mi)
                    #pragma unroll
                    for (int g = 0; g < 4; ++g) {
                        MMA(acc[mi][2*g+0], al[mi], bh[g][0], bh[g][2]);
                        MMA(acc[mi][2*g+1], al[mi], bh[g][1], bh[g][3]);
                    }
            }
        }
    }

    // ---- epilogue
    const int g4 = lane >> 2, t4 = lane & 3;
    #pragma unroll
    for (int mi = 0; mi < 2; ++mi) {
        #pragma unroll
        for (int nj = 0; nj < 8; ++nj) {
            const int r0 = mBase + wm*32 + mi*16 + g4;
            const int c0 = nBase + wn*64 + nj*8 + t4*2;
            float v0 = acc[mi][nj][0] * alpha, v1 = acc[mi][nj][1] * alpha;
            float v2 = acc[mi][nj][2] * alpha, v3 = acc[mi][nj][3] * alpha;
            if (Cf) {
                *reinterpret_cast<float2*>(Cf + (size_t)r0 * ldc + c0)       = make_float2(v0, v1);
                *reinterpret_cast<float2*>(Cf + (size_t)(r0+8) * ldc + c0)   = make_float2(v2, v3);
            } else {
                __half h0 = __float2half(v0), h1 = __float2half(v1);
                __half h2 = __float2half(v2), h3 = __float2half(v3);
                *reinterpret_cast<unsigned*>(Ch + (size_t)r0 * ldc + c0)     = pack2(h0, h1);
                *reinterpret_cast<unsigned*>(Ch + (size_t)(r0+8) * ldc + c0) = pack2(h2, h3);
                if (Cl) {
                    *reinterpret_cast<unsigned*>(Cl + (size_t)r0 * ldc + c0) =
                        pack2(__float2half(v0 - __half2float(h0)),
                              __float2half(v1 - __half2float(h1)));
                    *reinterpret_cast<unsigned*>(Cl + (size_t)(r0+8) * ldc + c0) =
                        pack2(__float2half(v2 - __half2float(h2)),
                              __float2half(v3 - __half2float(h3)));
                }
            }
        }
    }
}

// ---------------------------------------------------------------- small kernels
__global__ __launch_bounds__(256) void build_c_split(const float4* __restrict__ s,
                                                     const float4* __restrict__ tg,
                                                     const float4* __restrict__ q)
{
    const size_t i = (size_t)blockIdx.x * blockDim.x + threadIdx.x;
    float4 a = s[i], b = tg[i];
    float4 r; r.x = a.x + b.x; r.y = a.y + b.y; r.z = a.z + b.z; r.w = a.w + b.w;
    wr_hl4(g_ch, g_cl, i * 4, r);
    float4 qq = q[i];
    wr_hl4(g_ch, g_cl, (size_t)BSQ * CDIM + i * 4, qq);
}

__global__ __launch_bounds__(256) void cvt_w(const float4* __restrict__ w,
                                             __half* __restrict__ H,
                                             __half* __restrict__ L)
{
    const size_t i = (size_t)blockIdx.x * blockDim.x + threadIdx.x;
    wr_hl4(H, L, i * 4, w[i]);
}

// transpose fp32 [R x C] -> f16 hi/lo [C x R] (ol may be null)
__global__ __launch_bounds__(256) void transpose_cvt(const float* __restrict__ in,
                                                     __half* __restrict__ oh,
                                                     __half* __restrict__ ol,
                                                     int R, int C)
{
    __shared__ float t[32][33];
    const int tx = threadIdx.x, ty = threadIdx.y;
    const int x = blockIdx.x * 32 + tx;
    #pragma unroll
    for (int j = 0; j < 4; ++j) {
        const int y = blockIdx.y * 32 + ty + j * 8;
        t[ty + j*8][tx] = in[(size_t)y * C + x];
    }
    __syncthreads();
    const int ox = blockIdx.y * 32 + tx;
    #pragma unroll
    for (int j = 0; j < 4; ++j) {
        const int oy = blockIdx.x * 32 + ty + j * 8;
        float v = t[tx][ty + j*8];
        __half h = __float2half(v);
        oh[(size_t)oy * R + ox] = h;
        if (ol) ol[(size_t)oy * R + ox] = __float2half(v - __half2float(h));
    }
}

// softmax over 8192-wide rows; emit needed quadrant as f16 (hi only)
__global__ __launch_bounds__(512) void softmax_fused(const float* __restrict__ S)
{
    const float* p = S + (size_t)blockIdx.x * NTOT;
    const int t = threadIdx.x;
    float v[16];
    float m = -1e30f;
    #pragma unroll
    for (int i = 0; i < 16; ++i) { v[i] = p[t + i * 512]; m = fmaxf(m, v[i]); }

    __shared__ float red[16];
    #pragma unroll
    for (int o = 16; o; o >>= 1) m = fmaxf(m, __shfl_xor_sync(0xffffffffu, m, o));
    if ((t & 31) == 0) red[t >> 5] = m;
    __syncthreads();
    float mm = red[0];
    #pragma unroll
    for (int i = 1; i < 16; ++i) mm = fmaxf(mm, red[i]);

    float sum = 0.0f;
    #pragma unroll
    for (int i = 0; i < 16; ++i) { v[i] = __expf(v[i] - mm); sum += v[i]; }
    #pragma unroll
    for (int o = 16; o; o >>= 1) sum += __shfl_xor_sync(0xffffffffu, sum, o);
    __syncthreads();
    if ((t & 31) == 0) red[t >> 5] = sum;
    __syncthreads();
    float tot = 0.0f;
    #pragma unroll
    for (int i = 0; i < 16; ++i) tot += red[i];
    const float rcp = 1.0f / tot;

    if (blockIdx.x < BSQ) {
        const size_t rb = (size_t)blockIdx.x * BSQ;
        #pragma unroll
        for (int i = 8; i < 16; ++i) {
            const int col = t + (i - 8) * 512;
            g_pcqh[rb + col] = __float2half(v[i] * rcp);
        }
    } else {
        const size_t rb = (size_t)(blockIdx.x - BSQ) * BSQ;
        #pragma unroll
        for (int i = 0; i < 8; ++i) {
            const int col = t + i * 512;
            g_pqch[rb + col] = __float2half(v[i] * rcp);
        }
    }
}

// ---------------------------------------------------------------- host
static void run_gemm(const __half* Ah, const __half* Al, size_t ldA,
                     const __half* Bh, const __half* Bl, size_t ldB,
                     int M, int N, int K, float alpha,
                     float* Cf, __half* Ch, __half* Cl, int ldc,
                     int nprod)
{
    dim3 grid(N / 128, M / 128);
    if (nprod == 1)
        hmma_gemm<1><<<grid, 256, SMEM_GEMM>>>(Ah, Al, ldA, Bh, Bl, ldB, K, alpha, Cf, Ch, Cl, ldc);
    else if (nprod == 2)
        hmma_gemm<2><<<grid, 256, SMEM_GEMM>>>(Ah, Al, ldA, Bh, Bl, ldB, K, alpha, Cf, Ch, Cl, ldc);
    else
        hmma_gemm<3><<<grid, 256, SMEM_GEMM>>>(Ah, Al, ldA, Bh, Bl, ldB, K, alpha, Cf, Ch, Cl, ldc);
}

extern "C" void kernel_launch(void* const* d_in, const int* in_sizes, int n_in,
                              void* d_out, int out_size)
{
    const float* query = (const float*)d_in[0];
    const float* s     = (const float*)d_in[1];
    const float* tg    = (const float*)d_in[2];
    const float* Wqkv  = (const float*)d_in[3];
    const float* Wps   = (const float*)d_in[4];
    const float* Wpq   = (const float*)d_in[5];
    float* out = (float*)d_out;

    void* p;
    cudaGetSymbolAddress(&p, g_S);    float* S = (float*)p;
    cudaGetSymbolAddress(&p, g_ch);   __half* ch = (__half*)p;
    cudaGetSymbolAddress(&p, g_cl);   __half* cl = (__half*)p;
    cudaGetSymbolAddress(&p, g_wqTh); __half* wqTh = (__half*)p;
    cudaGetSymbolAddress(&p, g_wqTl); __half* wqTl = (__half*)p;
    cudaGetSymbolAddress(&p, g_wkTh); __half* wkTh = (__half*)p;
    cudaGetSymbolAddress(&p, g_wkTl); __half* wkTl = (__half*)p;
    cudaGetSymbolAddress(&p, g_mwth); __half* mwth = (__half*)p;
    cudaGetSymbolAddress(&p, g_mwtl); __half* mwtl = (__half*)p;
    cudaGetSymbolAddress(&p, g_zh);   __half* zh = (__half*)p;
    cudaGetSymbolAddress(&p, g_zl);   __half* zl = (__half*)p;
    cudaGetSymbolAddress(&p, g_wpsh); __half* wpsh = (__half*)p;
    cudaGetSymbolAddress(&p, g_wpsl); __half* wpsl = (__half*)p;
    cudaGetSymbolAddress(&p, g_wpqh); __half* wpqh = (__half*)p;
    cudaGetSymbolAddress(&p, g_wpql); __half* wpql = (__half*)p;
    cudaGetSymbolAddress(&p, g_pcqh); __half* pcqh = (__half*)p;
    cudaGetSymbolAddress(&p, g_pqch); __half* pqch = (__half*)p;
    cudaGetSymbolAddress(&p, g_qTh);  __half* qTh = (__half*)p;
    cudaGetSymbolAddress(&p, g_sTh);  __half* sTh = (__half*)p;
    cudaGetSymbolAddress(&p, g_t0h);  __half* t0h = (__half*)p;
    cudaGetSymbolAddress(&p, g_t1h);  __half* t1h = (__half*)p;

    cudaFuncSetAttribute(hmma_gemm<3>, cudaFuncAttributeMaxDynamicSharedMemorySize, SMEM_GEMM);
    cudaFuncSetAttribute(hmma_gemm<2>, cudaFuncAttributeMaxDynamicSharedMemorySize, SMEM_GEMM);
    cudaFuncSetAttribute(hmma_gemm<1>, cudaFuncAttributeMaxDynamicSharedMemorySize, SMEM_GEMM);

    // 1) c = [s+TG ; query] -> f16 hi/lo
    build_c_split<<<(BSQ * CDIM / 4) / 256, 256>>>(
        (const float4*)s, (const float4*)tg, (const float4*)query);

    // 2) projection weight conversions (hi/lo — proj is 2-prod)
    cvt_w<<<(HD * HD / 4) / 256, 256>>>((const float4*)Wps, wpsh, wpsl);
    cvt_w<<<(HD * HD / 4) / 256, 256>>>((const float4*)Wpq, wpqh, wpql);

    // 3) transposes: query^T, s^T hi-only (P@V is 1-prod); Wq^T, Wk^T hi/lo
    transpose_cvt<<<dim3(CDIM / 32, BSQ / 32), dim3(32, 8)>>>(query, qTh, nullptr, BSQ, CDIM);
    transpose_cvt<<<dim3(CDIM / 32, BSQ / 32), dim3(32, 8)>>>(s, sTh, nullptr, BSQ, CDIM);
    transpose_cvt<<<dim3(CDIM / 32, HD / 32), dim3(32, 8)>>>(Wqkv, wqTh, wqTl, HD, CDIM);
    transpose_cvt<<<dim3(CDIM / 32, HD / 32), dim3(32, 8)>>>(Wqkv + (size_t)HD * CDIM,
                                                             wkTh, wkTl, HD, CDIM);

    // 4) MwT = SCALE^2 * Wk^T @ Wq  -> f16 hi/lo [1024 x 1024]  (3-prod)
    run_gemm(wkTh, wkTl, HD, wqTh, wqTl, HD,
             CDIM, CDIM, HD, SCALE2_F, nullptr, mwth, mwtl, CDIM, 3);

    // 5) Z = c @ MwT^T  -> f16 hi/lo [8192 x 1024]  (3-prod, logit path)
    run_gemm(ch, cl, CDIM, mwth, mwtl, CDIM,
             NTOT, HD, CDIM, 1.0f, nullptr, zh, zl, HD, 3);

    // 6) S = Z @ c^T (f32) [8192 x 8192] — 1-prod (zh @ ch, both f16)
    run_gemm(zh, nullptr, HD, ch, nullptr, CDIM,
             NTOT, NTOT, HD, 1.0f, S, nullptr, nullptr, NTOT, 1);

    // 7) softmax + quadrant split -> f16 (hi only)
    softmax_fused<<<NTOT, 512>>>(S);

    // 8) t0 = Pcq @ query ; t1 = Pqc @ s — 1-prod (pure f16 hh)
    run_gemm(pcqh, nullptr, BSQ, qTh, nullptr, BSQ,
             BSQ, HD, BSQ, 1.0f, nullptr, t0h, nullptr, HD, 1);
    run_gemm(pqch, nullptr, BSQ, sTh, nullptr, BSQ,
             BSQ, HD, BSQ, 1.0f, nullptr, t1h, nullptr, HD, 1);

    // 9) x_s = t0 @ Wps^T ; x_q = t1 @ Wpq^T (f32 out) — 2-prod (t f16)
    run_gemm(t0h, nullptr, HD, wpsh, wpsl, HD,
             BSQ, HD, HD, 1.0f, out, nullptr, nullptr, HD, 2);
    run_gemm(t1h, nullptr, HD, wpqh, wpql, HD,
             BSQ, HD, HD, 1.0f, out + (size_t)BSQ * HD, nullptr, nullptr, HD, 2);
}

// round 15
// speedup vs baseline: 2.4107x; 1.0890x over previous
#include <cuda_runtime.h>
#include <cuda_fp16.h>
#include <cstdint>
#include <math.h>

// ---------------------------------------------------------------- constants
#define BSQ   4096
#define CDIM  1024
#define NTOT  8192
#define HD    1024
#define SCALE2_F 0.03125f              // (1024^-0.25)^2 = 1/32

// GEMM config: CTA 128x128, k-chunk 64
// 3-prod: 4 mats/stage x3 stages. 2-prod: 3x4. 1-prod: 2x6. Same smem.
#define ROWB      144                  // smem row stride bytes (64 f16 + pad)
#define MAT_BYTES (128 * ROWB)         // 18432
#define SMEM_GEMM (12 * MAT_BYTES)     // 221184

// ---------------------------------------------------------------- scratch
static __device__ float   g_S  [(size_t)NTOT*NTOT];            // 256 MB
static __device__ __half  g_ch [(size_t)NTOT*CDIM],  g_cl [(size_t)NTOT*CDIM];
static __device__ __half  g_wqTh[(size_t)CDIM*HD],   g_wqTl[(size_t)CDIM*HD];
static __device__ __half  g_wkTh[(size_t)CDIM*HD],   g_wkTl[(size_t)CDIM*HD];
static __device__ __half  g_mwth[(size_t)HD*CDIM],   g_mwtl[(size_t)HD*CDIM];
static __device__ __half  g_zh [(size_t)NTOT*HD],    g_zl [(size_t)NTOT*HD];
static __device__ __half  g_wpsh[(size_t)HD*HD],     g_wpsl[(size_t)HD*HD];
static __device__ __half  g_wpqh[(size_t)HD*HD],     g_wpql[(size_t)HD*HD];
static __device__ __half  g_pcqh[(size_t)BSQ*BSQ];             // P quadrants, f16
static __device__ __half  g_pqch[(size_t)BSQ*BSQ];
static __device__ __half  g_qTh[(size_t)CDIM*BSQ];             // query^T, s^T f16 (hi)
static __device__ __half  g_sTh[(size_t)CDIM*BSQ];
static __device__ __half  g_t0h[(size_t)BSQ*HD];               // t, f16
static __device__ __half  g_t1h[(size_t)BSQ*HD];

// ---------------------------------------------------------------- helpers
__device__ __forceinline__ uint32_t smem_u32(const void* p) {
    uint32_t a;
    asm("{ .reg .u64 t; cvta.to.shared.u64 t, %1; cvt.u32.u64 %0, t; }" : "=r"(a) : "l"(p));
    return a;
}
__device__ __forceinline__ void cp16(uint32_t dst, const void* src) {
    asm volatile("cp.async.cg.shared.global [%0], [%1], 16;" :: "r"(dst), "l"(src) : "memory");
}
#define CP_COMMIT() asm volatile("cp.async.commit_group;" ::: "memory")

#define LDSM4(r, a) \
    asm volatile("ldmatrix.sync.aligned.m8n8.x4.shared.b16 {%0,%1,%2,%3}, [%4];" \
        : "=r"((r)[0]), "=r"((r)[1]), "=r"((r)[2]), "=r"((r)[3]) : "r"(a))

#define MMA(d, a, b0, b1) \
    asm volatile("mma.sync.aligned.m16n8k16.row.col.f32.f16.f16.f32 " \
        "{%0,%1,%2,%3}, {%4,%5,%6,%7}, {%8,%9}, {%0,%1,%2,%3};" \
        : "+f"((d)[0]), "+f"((d)[1]), "+f"((d)[2]), "+f"((d)[3]) \
        : "r"((a)[0]), "r"((a)[1]), "r"((a)[2]), "r"((a)[3]), "r"(b0), "r"(b1))

__device__ __forceinline__ unsigned pack2(__half a, __half b) {
    unsigned short x = *reinterpret_cast<unsigned short*>(&a);
    unsigned short y = *reinterpret_cast<unsigned short*>(&b);
    return (unsigned)x | ((unsigned)y << 16);
}
__device__ __forceinline__ void wr_hl4(__half* H, __half* L, size_t off, float4 v) {
    __half h0 = __float2half(v.x), h1 = __float2half(v.y);
    __half h2 = __float2half(v.z), h3 = __float2half(v.w);
    uint2 hu; hu.x = pack2(h0, h1); hu.y = pack2(h2, h3);
    uint2 lu;
    lu.x = pack2(__float2half(v.x - __half2float(h0)),
                 __float2half(v.y - __half2float(h1)));
    lu.y = pack2(__float2half(v.z - __half2float(h2)),
                 __float2half(v.w - __half2float(h3)));
    *reinterpret_cast<uint2*>(H + off) = hu;
    *reinterpret_cast<uint2*>(L + off) = lu;
}

// ---------------------------------------------------------------- HMMA GEMM
// NPROD==3: D = alpha*(Ah@Bh^T + Ah@Bl^T + Al@Bh^T)   (~2^-23 eff.)
// NPROD==2: D = alpha*(Ah@Bh^T + Ah@Bl^T)             (A rounded, ~2^-12)
// NPROD==1: D = alpha*(Ah@Bh^T)                       (both rounded, ~2^-12 each)
// A: [M][K] row-major f16 (ldA), B: [N][K] row-major f16 (ldB).
// Out: Cf (f32) if non-null, else Ch (+ Cl when non-null) f16.
// K % 64 == 0, K >= 64*(NST-1).
template <int NPROD>
__global__ __launch_bounds__(256, 1) void hmma_gemm(
    const __half* __restrict__ Ah, const __half* __restrict__ Al, size_t ldA,
    const __half* __restrict__ Bh, const __half* __restrict__ Bl, size_t ldB,
    int K, float alpha,
    float* __restrict__ Cf, __half* __restrict__ Ch, __half* __restrict__ Cl,
    int ldc)
{
    constexpr int NMAT = (NPROD == 3) ? 4 : (NPROD == 2 ? 3 : 2);
    constexpr int NST  = 12 / NMAT;                   // 3, 4, 6
    constexpr int STG  = NMAT * MAT_BYTES;
    constexpr int BOFF = (NPROD == 3) ? 2 * MAT_BYTES : MAT_BYTES;

    extern __shared__ char dynsm[];
    const uint32_t sbase = smem_u32(dynsm);

    const int tid  = threadIdx.x;
    const int wid  = tid >> 5;
    const int lane = tid & 31;
    const int mBase = blockIdx.y * 128;
    const int nBase = blockIdx.x * 128;
    const int nch = K >> 6;

    const int wm = wid & 3, wn = wid >> 2;

    // ---- load geometry
    const __half* gsrc;
    size_t gld = 0;
    uint32_t sdst0;
    bool do_load = true;
    bool two_rows;
    if (NPROD == 1) {
        const int mat = tid >> 7;            // 0: Ah, 1: Bh
        const int row = tid & 127;
        gsrc = (mat == 0) ? Ah + (size_t)(mBase + row) * ldA
                          : Bh + (size_t)(nBase + row) * ldB;
        sdst0 = sbase + mat * MAT_BYTES + row * ROWB;
        two_rows = false;
    } else {
        const int sel  = tid >> 6;
        const int lrow = (tid & 63) * 2;
        if (sel == 0)      { gsrc = Ah + (size_t)(mBase + lrow) * ldA; gld = ldA; }
        else if (sel == 1) { gsrc = Al ? Al + (size_t)(mBase + lrow) * ldA : Ah; gld = ldA; }
        else if (sel == 2) { gsrc = Bh + (size_t)(nBase + lrow) * ldB; gld = ldB; }
        else               { gsrc = Bl + (size_t)(nBase + lrow) * ldB; gld = ldB; }
        const int dsel = (NPROD == 3) ? sel : (sel == 0 ? 0 : (sel == 2 ? 1 : 2));
        sdst0 = sbase + dsel * MAT_BYTES + lrow * ROWB;
        do_load = (NPROD == 3) || (sel != 1);
        two_rows = true;
    }

    #define LOAD_CHUNK(stg, k0) do {                                    \
        if (do_load) {                                                   \
            const uint32_t _d = sdst0 + (stg) * STG;                     \
            const __half* _s = gsrc + (k0);                              \
            _Pragma("unroll")                                            \
            for (int _j = 0; _j < 8; ++_j) {                             \
                cp16(_d + _j * 16, _s + _j * 8);                         \
                if (two_rows) cp16(_d + ROWB + _j * 16, _s + gld + _j * 8); \
            }                                                            \
        }                                                                \
    } while (0)

    const int l15 = lane & 15;
    const int lc8 = (lane >> 4) << 3;

    float acc[2][8][4];
    #pragma unroll
    for (int i = 0; i < 2; ++i)
        #pragma unroll
        for (int j = 0; j < 8; ++j)
            #pragma unroll
            for (int q = 0; q < 4; ++q) acc[i][j][q] = 0.0f;

    // prologue: NST-1 chunks in flight
    #pragma unroll
    for (int j = 0; j < NST - 1; ++j) {
        LOAD_CHUNK(j, j << 6);
        CP_COMMIT();
    }

    for (int i = 0; i < nch; ++i) {
        asm volatile("cp.async.wait_group %0;" :: "n"(NST - 2) : "memory");
        __syncthreads();
        if (i + NST - 1 < nch) { LOAD_CHUNK((i + NST - 1) % NST, (i + NST - 1) << 6); }
        CP_COMMIT();

        const uint32_t stg = sbase + (i % NST) * STG;
        #pragma unroll
        for (int kk = 0; kk < 64; kk += 16) {
            uint32_t ah[2][4], al[2][4], bh[4][4], bl[4][4];
            #pragma unroll
            for (int mi = 0; mi < 2; ++mi) {
                const uint32_t ao = stg + (wm*32 + mi*16 + l15) * ROWB + (kk + lc8) * 2;
                LDSM4(ah[mi], ao);
                if (NPROD == 3) LDSM4(al[mi], ao + MAT_BYTES);
            }
            #pragma unroll
            for (int g = 0; g < 4; ++g) {
                const uint32_t bo = stg + BOFF + (wn*64 + g*16 + l15) * ROWB + (kk + lc8) * 2;
                LDSM4(bh[g], bo);
                if (NPROD >= 2) LDSM4(bl[g], bo + MAT_BYTES);
            }
            // product-major: dependent MMAs on same acc are 16 apart
            #pragma unroll
            for (int mi = 0; mi < 2; ++mi)
                #pragma unroll
                for (int g = 0; g < 4; ++g) {
                    MMA(acc[mi][2*g+0], ah[mi], bh[g][0], bh[g][2]);
                    MMA(acc[mi][2*g+1], ah[mi], bh[g][1], bh[g][3]);
                }
            if (NPROD >= 2) {
                #pragma unroll
                for (int mi = 0; mi < 2; ++mi)
                    #pragma unroll
                    for (int g = 0; g < 4; ++g) {
                        MMA(acc[mi][2*g+0], ah[mi], bl[g][0], bl[g][2]);
                        MMA(acc[mi][2*g+1], ah[mi], bl[g][1], bl[g][3]);
                    }
            }
            if (NPROD == 3) {
                #pragma unroll
                for (int mi = 0; mi < 2; ++mi)
                    #pragma unroll
                    for (int g = 0; g < 4; ++g) {
                        MMA(acc[mi][2*g+0], al[mi], bh[g][0], bh[g][2]);
                        MMA(acc[mi][2*g+1], al[mi], bh[g][1], bh[g][3]);
                    }
            }
        }
    }

    // ---- epilogue
    const int g4 = lane >> 2, t4 = lane & 3;
    #pragma unroll
    for (int mi = 0; mi < 2; ++mi) {
        #pragma unroll
        for (int nj = 0; nj < 8; ++nj) {
            const int r0 = mBase + wm*32 + mi*16 + g4;
            const int c0 = nBase + wn*64 + nj*8 + t4*2;
            float v0 = acc[mi][nj][0] * alpha, v1 = acc[mi][nj][1] * alpha;
            float v2 = acc[mi][nj][2] * alpha, v3 = acc[mi][nj][3] * alpha;
            if (Cf) {
                *reinterpret_cast<float2*>(Cf + (size_t)r0 * ldc + c0)       = make_float2(v0, v1);
                *reinterpret_cast<float2*>(Cf + (size_t)(r0+8) * ldc + c0)   = make_float2(v2, v3);
            } else {
                __half h0 = __float2half(v0), h1 = __float2half(v1);
                __half h2 = __float2half(v2), h3 = __float2half(v3);
                *reinterpret_cast<unsigned*>(Ch + (size_t)r0 * ldc + c0)     = pack2(h0, h1);
                *reinterpret_cast<unsigned*>(Ch + (size_t)(r0+8) * ldc + c0) = pack2(h2, h3);
                if (Cl) {
                    *reinterpret_cast<unsigned*>(Cl + (size_t)r0 * ldc + c0) =
                        pack2(__float2half(v0 - __half2float(h0)),
                              __float2half(v1 - __half2float(h1)));
                    *reinterpret_cast<unsigned*>(Cl + (size_t)(r0+8) * ldc + c0) =
                        pack2(__float2half(v2 - __half2float(h2)),
                              __float2half(v3 - __half2float(h3)));
                }
            }
        }
    }
}

// ---------------------------------------------------------------- small kernels
__global__ __launch_bounds__(256) void build_c_split(const float4* __restrict__ s,
                                                     const float4* __restrict__ tg,
                                                     const float4* __restrict__ q)
{
    const size_t i = (size_t)blockIdx.x * blockDim.x + threadIdx.x;
    float4 a = s[i], b = tg[i];
    float4 r; r.x = a.x + b.x; r.y = a.y + b.y; r.z = a.z + b.z; r.w = a.w + b.w;
    wr_hl4(g_ch, g_cl, i * 4, r);
    float4 qq = q[i];
    wr_hl4(g_ch, g_cl, (size_t)BSQ * CDIM + i * 4, qq);
}

__global__ __launch_bounds__(256) void cvt_w(const float4* __restrict__ w,
                                             __half* __restrict__ H,
                                             __half* __restrict__ L)
{
    const size_t i = (size_t)blockIdx.x * blockDim.x + threadIdx.x;
    wr_hl4(H, L, i * 4, w[i]);
}

// transpose fp32 [R x C] -> f16 hi/lo [C x R] (ol may be null)
__global__ __launch_bounds__(256) void transpose_cvt(const float* __restrict__ in,
                                                     __half* __restrict__ oh,
                                                     __half* __restrict__ ol,
                                                     int R, int C)
{
    __shared__ float t[32][33];
    const int tx = threadIdx.x, ty = threadIdx.y;
    const int x = blockIdx.x * 32 + tx;
    #pragma unroll
    for (int j = 0; j < 4; ++j) {
        const int y = blockIdx.y * 32 + ty + j * 8;
        t[ty + j*8][tx] = in[(size_t)y * C + x];
    }
    __syncthreads();
    const int ox = blockIdx.y * 32 + tx;
    #pragma unroll
    for (int j = 0; j < 4; ++j) {
        const int oy = blockIdx.x * 32 + ty + j * 8;
        float v = t[tx][ty + j*8];
        __half h = __float2half(v);
        oh[(size_t)oy * R + ox] = h;
        if (ol) ol[(size_t)oy * R + ox] = __float2half(v - __half2float(h));
    }
}

// softmax over 8192-wide rows; emit needed quadrant as f16 (hi only)
__global__ __launch_bounds__(512) void softmax_fused(const float* __restrict__ S)
{
    const float* p = S + (size_t)blockIdx.x * NTOT;
    const int t = threadIdx.x;
    float v[16];
    float m = -1e30f;
    #pragma unroll
    for (int i = 0; i < 16; ++i) { v[i] = p[t + i * 512]; m = fmaxf(m, v[i]); }

    __shared__ float red[16];
    #pragma unroll
    for (int o = 16; o; o >>= 1) m = fmaxf(m, __shfl_xor_sync(0xffffffffu, m, o));
    if ((t & 31) == 0) red[t >> 5] = m;
    __syncthreads();
    float mm = red[0];
    #pragma unroll
    for (int i = 1; i < 16; ++i) mm = fmaxf(mm, red[i]);

    float sum = 0.0f;
    #pragma unroll
    for (int i = 0; i < 16; ++i) { v[i] = __expf(v[i] - mm); sum += v[i]; }
    #pragma unroll
    for (int o = 16; o; o >>= 1) sum += __shfl_xor_sync(0xffffffffu, sum, o);
    __syncthreads();
    if ((t & 31) == 0) red[t >> 5] = sum;
    __syncthreads();
    float tot = 0.0f;
    #pragma unroll
    for (int i = 0; i < 16; ++i) tot += red[i];
    const float rcp = 1.0f / tot;

    if (blockIdx.x < BSQ) {
        const size_t rb = (size_t)blockIdx.x * BSQ;
        #pragma unroll
        for (int i = 8; i < 16; ++i) {
            const int col = t + (i - 8) * 512;
            g_pcqh[rb + col] = __float2half(v[i] * rcp);
        }
    } else {
        const size_t rb = (size_t)(blockIdx.x - BSQ) * BSQ;
        #pragma unroll
        for (int i = 0; i < 8; ++i) {
            const int col = t + i * 512;
            g_pqch[rb + col] = __float2half(v[i] * rcp);
        }
    }
}

// ---------------------------------------------------------------- host
static void run_gemm(const __half* Ah, const __half* Al, size_t ldA,
                     const __half* Bh, const __half* Bl, size_t ldB,
                     int M, int N, int K, float alpha,
                     float* Cf, __half* Ch, __half* Cl, int ldc,
                     int nprod)
{
    dim3 grid(N / 128, M / 128);
    if (nprod == 1)
        hmma_gemm<1><<<grid, 256, SMEM_GEMM>>>(Ah, Al, ldA, Bh, Bl, ldB, K, alpha, Cf, Ch, Cl, ldc);
    else if (nprod == 2)
        hmma_gemm<2><<<grid, 256, SMEM_GEMM>>>(Ah, Al, ldA, Bh, Bl, ldB, K, alpha, Cf, Ch, Cl, ldc);
    else
        hmma_gemm<3><<<grid, 256, SMEM_GEMM>>>(Ah, Al, ldA, Bh, Bl, ldB, K, alpha, Cf, Ch, Cl, ldc);
}

extern "C" void kernel_launch(void* const* d_in, const int* in_sizes, int n_in,
                              void* d_out, int out_size)
{
    const float* query = (const float*)d_in[0];
    const float* s     = (const float*)d_in[1];
    const float* tg    = (const float*)d_in[2];
    const float* Wqkv  = (const float*)d_in[3];
    const float* Wps   = (const float*)d_in[4];
    const float* Wpq   = (const float*)d_in[5];
    float* out = (float*)d_out;

    void* p;
    cudaGetSymbolAddress(&p, g_S);    float* S = (float*)p;
    cudaGetSymbolAddress(&p, g_ch);   __half* ch = (__half*)p;
    cudaGetSymbolAddress(&p, g_cl);   __half* cl = (__half*)p;
    cudaGetSymbolAddress(&p, g_wqTh); __half* wqTh = (__half*)p;
    cudaGetSymbolAddress(&p, g_wqTl); __half* wqTl = (__half*)p;
    cudaGetSymbolAddress(&p, g_wkTh); __half* wkTh = (__half*)p;
    cudaGetSymbolAddress(&p, g_wkTl); __half* wkTl = (__half*)p;
    cudaGetSymbolAddress(&p, g_mwth); __half* mwth = (__half*)p;
    cudaGetSymbolAddress(&p, g_mwtl); __half* mwtl = (__half*)p;
    cudaGetSymbolAddress(&p, g_zh);   __half* zh = (__half*)p;
    cudaGetSymbolAddress(&p, g_zl);   __half* zl = (__half*)p;
    cudaGetSymbolAddress(&p, g_wpsh); __half* wpsh = (__half*)p;
    cudaGetSymbolAddress(&p, g_wpsl); __half* wpsl = (__half*)p;
    cudaGetSymbolAddress(&p, g_wpqh); __half* wpqh = (__half*)p;
    cudaGetSymbolAddress(&p, g_wpql); __half* wpql = (__half*)p;
    cudaGetSymbolAddress(&p, g_pcqh); __half* pcqh = (__half*)p;
    cudaGetSymbolAddress(&p, g_pqch); __half* pqch = (__half*)p;
    cudaGetSymbolAddress(&p, g_qTh);  __half* qTh = (__half*)p;
    cudaGetSymbolAddress(&p, g_sTh);  __half* sTh = (__half*)p;
    cudaGetSymbolAddress(&p, g_t0h);  __half* t0h = (__half*)p;
    cudaGetSymbolAddress(&p, g_t1h);  __half* t1h = (__half*)p;

    cudaFuncSetAttribute(hmma_gemm<3>, cudaFuncAttributeMaxDynamicSharedMemorySize, SMEM_GEMM);
    cudaFuncSetAttribute(hmma_gemm<2>, cudaFuncAttributeMaxDynamicSharedMemorySize, SMEM_GEMM);
    cudaFuncSetAttribute(hmma_gemm<1>, cudaFuncAttributeMaxDynamicSharedMemorySize, SMEM_GEMM);

    // 1) c = [s+TG ; query] -> f16 hi/lo
    build_c_split<<<(BSQ * CDIM / 4) / 256, 256>>>(
        (const float4*)s, (const float4*)tg, (const float4*)query);

    // 2) projection weight conversions (hi-only suffices; lo kept unused)
    cvt_w<<<(HD * HD / 4) / 256, 256>>>((const float4*)Wps, wpsh, wpsl);
    cvt_w<<<(HD * HD / 4) / 256, 256>>>((const float4*)Wpq, wpqh, wpql);

    // 3) transposes: query^T, s^T hi-only (P@V is 1-prod); Wq^T, Wk^T hi/lo
    transpose_cvt<<<dim3(CDIM / 32, BSQ / 32), dim3(32, 8)>>>(query, qTh, nullptr, BSQ, CDIM);
    transpose_cvt<<<dim3(CDIM / 32, BSQ / 32), dim3(32, 8)>>>(s, sTh, nullptr, BSQ, CDIM);
    transpose_cvt<<<dim3(CDIM / 32, HD / 32), dim3(32, 8)>>>(Wqkv, wqTh, wqTl, HD, CDIM);
    transpose_cvt<<<dim3(CDIM / 32, HD / 32), dim3(32, 8)>>>(Wqkv + (size_t)HD * CDIM,
                                                             wkTh, wkTl, HD, CDIM);

    // 4) MwT = SCALE^2 * Wk^T @ Wq  -> f16 hi/lo [1024 x 1024]  (3-prod)
    run_gemm(wkTh, wkTl, HD, wqTh, wqTl, HD,
             CDIM, CDIM, HD, SCALE2_F, nullptr, mwth, mwtl, CDIM, 3);

    // 5) Z = c @ MwT^T  -> f16 hi/lo [8192 x 1024]  — 2-prod (ch @ (MwT_h+MwT_l))
    run_gemm(ch, nullptr, CDIM, mwth, mwtl, CDIM,
             NTOT, HD, CDIM, 1.0f, nullptr, zh, zl, HD, 2);

    // 6) S = Z @ c^T (f32) [8192 x 8192] — 1-prod (zh @ ch, both f16)
    run_gemm(zh, nullptr, HD, ch, nullptr, CDIM,
             NTOT, NTOT, HD, 1.0f, S, nullptr, nullptr, NTOT, 1);

    // 7) softmax + quadrant split -> f16 (hi only)
    softmax_fused<<<NTOT, 512>>>(S);

    // 8) t0 = Pcq @ query ; t1 = Pqc @ s — 1-prod (pure f16 hh)
    run_gemm(pcqh, nullptr, BSQ, qTh, nullptr, BSQ,
             BSQ, HD, BSQ, 1.0f, nullptr, t0h, nullptr, HD, 1);
    run_gemm(pqch, nullptr, BSQ, sTh, nullptr, BSQ,
             BSQ, HD, BSQ, 1.0f, nullptr, t1h, nullptr, HD, 1);

    // 9) x_s = t0 @ Wps^T ; x_q = t1 @ Wpq^T (f32 out) — 1-prod (both f16)
    run_gemm(t0h, nullptr, HD, wpsh, nullptr, HD,
             BSQ, HD, HD, 1.0f, out, nullptr, nullptr, HD, 1);
    run_gemm(t1h, nullptr, HD, wpqh, nullptr, HD,
             BSQ, HD, HD, 1.0f, out + (size_t)BSQ * HD, nullptr, nullptr, HD, 1);
}